// round 11
// baseline (speedup 1.0000x reference)
#include <cuda_runtime.h>
#include <cuda_fp16.h>
#include <math.h>
#include <stdint.h>

// Problem constants
#define N_INST 16384
#define BAGS   64
#define NMC    4
#define RF     512
#define D0     1024
#define D1     512
#define D2     256
#define NATT   4
#define DATT   32

// ---------------------------------------------------------------------------
// Scratch (static device globals: allocation-guard safe)
// ---------------------------------------------------------------------------
__device__ float g_z   [(size_t)NMC * N_INST * RF];
__device__ float g_expP[(size_t)N_INST * NMC * NATT];
__device__ float g_seg [BAGS * NMC * NATT];

__device__ __half g_Xh  [(size_t)N_INST * D0];
__device__ __half g_phih[(size_t)NMC * N_INST * 2 * RF];
__device__ __half g_h1h [(size_t)NMC * N_INST * D1];
__device__ __half g_embh[(size_t)NMC * N_INST * D2];
__device__ __half g_embl[(size_t)NMC * N_INST * D2];
// fp16 weights, TRANSPOSED [N][K]
__device__ __half g_O1T[(size_t)NMC * RF * D0];
__device__ __half g_O2T[(size_t)NMC * RF * D1];
__device__ __half g_W1T[(size_t)D1 * 2 * RF];
__device__ __half g_W2T[(size_t)D2 * 2 * RF];
__device__ __half g_WmT[(size_t)(NATT * DATT) * D2];

// ---------------------------------------------------------------------------
// Helpers
// ---------------------------------------------------------------------------
__device__ __forceinline__ void h_split(float v, __half& hi, __half& lo) {
    hi = __float2half_rn(v);
    lo = __float2half_rn(v - __half2float(hi));
}

#define CP_ASYNC16(smem_u32, gptr) \
    asm volatile("cp.async.cg.shared.global [%0], [%1], 16;\n" \
                 :: "r"(smem_u32), "l"(gptr))
#define CP_COMMIT()  asm volatile("cp.async.commit_group;\n")
#define CP_WAIT(n)   asm volatile("cp.async.wait_group %0;\n" :: "n"(n))

#define MMA_F16(c, a0, a1, a2, a3, b0, b1) \
    asm volatile("mma.sync.aligned.m16n8k16.row.col.f32.f16.f16.f32 " \
                 "{%0,%1,%2,%3}, {%4,%5,%6,%7}, {%8,%9}, {%0,%1,%2,%3};" \
                 : "+f"((c)[0]), "+f"((c)[1]), "+f"((c)[2]), "+f"((c)[3]) \
                 : "r"(a0), "r"(a1), "r"(a2), "r"(a3), "r"(b0), "r"(b1))

#define LDSM4(r0, r1, r2, r3, addr) \
    asm volatile("ldmatrix.sync.aligned.m8n8.x4.shared.b16 {%0,%1,%2,%3}, [%4];" \
                 : "=r"(r0), "=r"(r1), "=r"(r2), "=r"(r3) : "r"(addr))

// ---------------------------------------------------------------------------
// fp16 tensor-core GEMM, TERMS=1 (pure fp16) or TERMS=2 (A hi/lo split).
// C[M,N] = A[M,K] @ B^T (+bias); B TRANSPOSED [N][K].
// Block tile 256x128x32 (doubled M vs r9 -> half the L2 traffic per MMA),
// 256 threads, warp tile 64x64, 1 CTA/SM, 3-stage cp.async pipeline.
// ---------------------------------------------------------------------------
#define TBM 256
#define TBN 128
#define TBK 32
#define LDK 40
#define A_ELEMS (TBM * LDK)   // 10240
#define B_ELEMS (TBN * LDK)   // 5120
#define NBUF 3

template<int TERMS>
__global__ __launch_bounds__(256, 1) void f16_gemm(
    const __half* __restrict__ Ah, const __half* __restrict__ Al,
    const __half* __restrict__ BhT,
    const float* __restrict__ bias,
    float* __restrict__ C, __half* __restrict__ Chi, __half* __restrict__ Clo,
    int M, int Ncols, int K,
    long long sA, long long sB, long long sC)
{
    constexpr int STAGE_ELEMS = TERMS * A_ELEMS + B_ELEMS;
    constexpr int B_OFF = TERMS * A_ELEMS;

    Ah  += (long long)blockIdx.z * sA;
    if (TERMS == 2) Al += (long long)blockIdx.z * sA;
    BhT += (long long)blockIdx.z * sB;
    if (C)   C   += (long long)blockIdx.z * sC;
    if (Chi) Chi += (long long)blockIdx.z * sC;
    if (Clo) Clo += (long long)blockIdx.z * sC;

    extern __shared__ __half smem[];

    const int tid  = threadIdx.x;
    const int wid  = tid >> 5;
    const int lane = tid & 31;
    const int wm   = (wid >> 1) * 64;   // 4 warp-rows of 64
    const int wn   = (wid & 1) * 64;    // 2 warp-cols of 64
    const int brow = blockIdx.y * TBM;
    const int bcol = blockIdx.x * TBN;
    const int lg   = lane >> 2;
    const int lq2  = (lane & 3) * 2;

    float acc[4][8][4];
#pragma unroll
    for (int mi = 0; mi < 4; mi++)
#pragma unroll
        for (int ni = 0; ni < 8; ni++)
#pragma unroll
            for (int j = 0; j < 4; j++) acc[mi][ni][j] = 0.f;

    const int nStages = K / TBK;
    const uint32_t smemBase = (uint32_t)__cvta_generic_to_shared(smem);

    const int stR = tid >> 1;            // 0..127
    const int stC = (tid & 1) * 16;

    auto stage_cpasync = [&](int buf, int k0) {
        const uint32_t sbb = smemBase + buf * (STAGE_ELEMS * 2);
        // A: 256 rows, two halves of 128
#pragma unroll
        for (int h = 0; h < 2; h++) {
            const int r = stR + h * 128;
#pragma unroll
            for (int i = 0; i < 2; i++) {
                const int c = stC + i * 8;
                CP_ASYNC16(sbb + (r * LDK + c) * 2,
                           Ah + (long long)(brow + r) * K + k0 + c);
                if (TERMS == 2)
                    CP_ASYNC16(sbb + (A_ELEMS + r * LDK + c) * 2,
                               Al + (long long)(brow + r) * K + k0 + c);
            }
        }
        // B: 128 rows
#pragma unroll
        for (int i = 0; i < 2; i++) {
            const int c = stC + i * 8;
            CP_ASYNC16(sbb + (B_OFF + stR * LDK + c) * 2,
                       BhT + (long long)(bcol + stR) * K + k0 + c);
        }
        CP_COMMIT();
    };

    const uint32_t aOff =
        (uint32_t)(((lane & 15) * LDK + (lane >> 4) * 8) * 2);
    const uint32_t bOff =
        (uint32_t)((((lane & 7) + ((lane >> 4) << 3)) * LDK +
                    (((lane >> 3) & 1) << 3)) * 2);

    stage_cpasync(0, 0);
    if (nStages > 1) stage_cpasync(1, TBK);

    int buf = 0;
    for (int s = 0; s < nStages; s++) {
        if (s + 2 < nStages) {
            stage_cpasync((s + 2) % NBUF, (s + 2) * TBK);
            CP_WAIT(2);
        } else if (s + 1 < nStages) {
            CP_WAIT(1);
        } else {
            CP_WAIT(0);
        }
        __syncthreads();

        const uint32_t tb  = smemBase + buf * (STAGE_ELEMS * 2);
        const uint32_t AhB = tb;
        const uint32_t AlB = tb + A_ELEMS * 2;
        const uint32_t BhB = tb + B_OFF * 2;

#pragma unroll
        for (int kk = 0; kk < 2; kk++) {
            const uint32_t kByte = kk * 16 * 2;
            uint32_t ah[4][4], al[4][4];
#pragma unroll
            for (int mi = 0; mi < 4; mi++) {
                const uint32_t rowB = (uint32_t)((wm + mi * 16) * LDK * 2);
                LDSM4(ah[mi][0], ah[mi][1], ah[mi][2], ah[mi][3],
                      AhB + rowB + aOff + kByte);
                if (TERMS == 2)
                    LDSM4(al[mi][0], al[mi][1], al[mi][2], al[mi][3],
                          AlB + rowB + aOff + kByte);
            }
#pragma unroll
            for (int p = 0; p < 4; p++) {
                const uint32_t nB = (uint32_t)((wn + p * 16) * LDK * 2);
                uint32_t bh0, bh1, bh2, bh3;
                LDSM4(bh0, bh1, bh2, bh3, BhB + nB + bOff + kByte);
#pragma unroll
                for (int mi = 0; mi < 4; mi++) {
                    float* c0 = acc[mi][p * 2];
                    float* c1 = acc[mi][p * 2 + 1];
                    MMA_F16(c0, ah[mi][0], ah[mi][1], ah[mi][2], ah[mi][3], bh0, bh1);
                    MMA_F16(c1, ah[mi][0], ah[mi][1], ah[mi][2], ah[mi][3], bh2, bh3);
                    if (TERMS == 2) {
                        MMA_F16(c0, al[mi][0], al[mi][1], al[mi][2], al[mi][3], bh0, bh1);
                        MMA_F16(c1, al[mi][0], al[mi][1], al[mi][2], al[mi][3], bh2, bh3);
                    }
                }
            }
        }
        __syncthreads();
        buf = (buf + 1 == NBUF) ? 0 : buf + 1;
    }

    // Epilogue
#pragma unroll
    for (int mi = 0; mi < 4; mi++) {
        const int row0 = brow + wm + mi * 16 + lg;
#pragma unroll
        for (int ni = 0; ni < 8; ni++) {
            const int col = bcol + wn + ni * 8 + lq2;
            float b0 = 0.f, b1 = 0.f;
            if (bias) { b0 = bias[col]; b1 = bias[col + 1]; }
            float v0 = acc[mi][ni][0] + b0;
            float v1 = acc[mi][ni][1] + b1;
            float v2 = acc[mi][ni][2] + b0;
            float v3 = acc[mi][ni][3] + b1;
            if (C) {
                *(float2*)(C + (long long)row0 * Ncols + col)       = make_float2(v0, v1);
                *(float2*)(C + (long long)(row0 + 8) * Ncols + col) = make_float2(v2, v3);
            }
            if (Chi && !Clo) {
                *(__half2*)(Chi + (long long)row0 * Ncols + col) =
                    __halves2half2(__float2half_rn(v0), __float2half_rn(v1));
                *(__half2*)(Chi + (long long)(row0 + 8) * Ncols + col) =
                    __halves2half2(__float2half_rn(v2), __float2half_rn(v3));
            } else if (Chi) {
                __half h0, l0, h1, l1, h2, l2, h3, l3;
                h_split(v0, h0, l0); h_split(v1, h1, l1);
                h_split(v2, h2, l2); h_split(v3, h3, l3);
                *(__half2*)(Chi + (long long)row0 * Ncols + col)       = __halves2half2(h0, h1);
                *(__half2*)(Clo + (long long)row0 * Ncols + col)       = __halves2half2(l0, l1);
                *(__half2*)(Chi + (long long)(row0 + 8) * Ncols + col) = __halves2half2(h2, h3);
                *(__half2*)(Clo + (long long)(row0 + 8) * Ncols + col) = __halves2half2(l2, l3);
            }
        }
    }
}

#define SMEM_T1 (NBUF * (1 * A_ELEMS + B_ELEMS) * 2)   // 92160
#define SMEM_T2 (NBUF * (2 * A_ELEMS + B_ELEMS) * 2)   // 153600

// ---------------------------------------------------------------------------
__global__ __launch_bounds__(256) void cvt_kernel(
    const float* __restrict__ src, __half* __restrict__ dst, long long n)
{
    long long i = (long long)blockIdx.x * blockDim.x + threadIdx.x;
    if (i < n) dst[i] = __float2half_rn(src[i]);
}

// fp32 [K][N] -> transposed fp16 [N][K], 32x32 smem-tiled.
__global__ __launch_bounds__(256) void splitT_kernel(
    const float* __restrict__ src, __half* __restrict__ hT, int K, int N)
{
    __shared__ float t[32][33];
    const long long boff = (long long)blockIdx.z * K * N;
    const int k0 = blockIdx.x * 32;
    const int n0 = blockIdx.y * 32;
    const int tx = threadIdx.x, ty = threadIdx.y;

#pragma unroll
    for (int i = 0; i < 32; i += 8)
        t[ty + i][tx] = src[boff + (long long)(k0 + ty + i) * N + n0 + tx];
    __syncthreads();
#pragma unroll
    for (int i = 0; i < 32; i += 8)
        hT[boff + (long long)(n0 + ty + i) * K + k0 + tx] =
            __float2half_rn(t[tx][ty + i]);
}

// ---------------------------------------------------------------------------
// Fused RBF random features + LayerNorm; writes fp16 phi.
// ---------------------------------------------------------------------------
__global__ __launch_bounds__(256) void rfln_kernel(
    const float* __restrict__ z, __half* __restrict__ phih)
{
    const long long row = blockIdx.x;
    const float* zr = z + row * RF;
    __half* ph = phih + row * (2 * RF);
    const int t = threadIdx.x;
    const float scale = 0.044194173824159216f;  // 1/sqrt(512)

    float za = zr[t];
    float zb = zr[t + 256];
    float ca = __cosf(za) * scale;
    float sa = __sinf(za) * scale;
    float cb = __cosf(zb) * scale;
    float sb2 = __sinf(zb) * scale;

    float sum = ca + cb + sa + sb2;
    float sq  = ca * ca + cb * cb + sa * sa + sb2 * sb2;

#pragma unroll
    for (int o = 16; o > 0; o >>= 1) {
        sum += __shfl_down_sync(0xffffffffu, sum, o);
        sq  += __shfl_down_sync(0xffffffffu, sq,  o);
    }
    __shared__ float s_sum[8], s_sq[8];
    __shared__ float s_mean, s_inv;
    const int warp = t >> 5, lane = t & 31;
    if (lane == 0) { s_sum[warp] = sum; s_sq[warp] = sq; }
    __syncthreads();
    if (t == 0) {
        float ts = 0.f, tq = 0.f;
#pragma unroll
        for (int i = 0; i < 8; i++) { ts += s_sum[i]; tq += s_sq[i]; }
        float mean = ts * (1.f / 1024.f);
        float var  = tq * (1.f / 1024.f) - mean * mean;
        s_mean = mean;
        s_inv  = rsqrtf(var + 1e-5f);
    }
    __syncthreads();
    const float mean = s_mean, inv = s_inv;
    ph[t]       = __float2half_rn((ca  - mean) * inv);
    ph[t + 256] = __float2half_rn((cb  - mean) * inv);
    ph[t + 512] = __float2half_rn((sa  - mean) * inv);
    ph[t + 768] = __float2half_rn((sb2 - mean) * inv);
}

// ---------------------------------------------------------------------------
// Attention scores from fp16 emb + per-bag exp-sum (atomics).
// ---------------------------------------------------------------------------
__global__ __launch_bounds__(256) void scores_kernel(
    const __half* __restrict__ embh, const float* __restrict__ Ws,
    const float* __restrict__ bs, const int* __restrict__ idx,
    float* __restrict__ expP, float* __restrict__ seg)
{
    const int gw   = (blockIdx.x * blockDim.x + threadIdx.x) >> 5;
    const int lane = threadIdx.x & 31;
    if (gw >= NMC * N_INST) return;
    const int m = gw / N_INST;
    const int n = gw - m * N_INST;
    const __half2* e = (const __half2*)(embh + (long long)gw * D2);

    float a0 = 0.f, a1 = 0.f, a2 = 0.f, a3 = 0.f;
    for (int d = lane; d < D2 / 2; d += 32) {
        __half2 ev = e[d];
        float e0 = __low2float(ev), e1 = __high2float(ev);
        float4 w0 = *(const float4*)(Ws + (2 * d) * 4);
        float4 w1 = *(const float4*)(Ws + (2 * d + 1) * 4);
        a0 = fmaf(e0, w0.x, fmaf(e1, w1.x, a0));
        a1 = fmaf(e0, w0.y, fmaf(e1, w1.y, a1));
        a2 = fmaf(e0, w0.z, fmaf(e1, w1.z, a2));
        a3 = fmaf(e0, w0.w, fmaf(e1, w1.w, a3));
    }
#pragma unroll
    for (int o = 16; o > 0; o >>= 1) {
        a0 += __shfl_down_sync(0xffffffffu, a0, o);
        a1 += __shfl_down_sync(0xffffffffu, a1, o);
        a2 += __shfl_down_sync(0xffffffffu, a2, o);
        a3 += __shfl_down_sync(0xffffffffu, a3, o);
    }
    if (lane == 0) {
        const int b = idx[n];
        const float inv16 = 0.0625f;
        float v0 = expf((a0 + bs[0]) * inv16);
        float v1 = expf((a1 + bs[1]) * inv16);
        float v2 = expf((a2 + bs[2]) * inv16);
        float v3 = expf((a3 + bs[3]) * inv16);
        float* ep = expP + ((long long)n * NMC + m) * NATT;
        ep[0] = v0; ep[1] = v1; ep[2] = v2; ep[3] = v3;
        float* sp = seg + ((long long)b * NMC + m) * NATT;
        atomicAdd(sp + 0, v0);
        atomicAdd(sp + 1, v1);
        atomicAdd(sp + 2, v2);
        atomicAdd(sp + 3, v3);
    }
}

// ---------------------------------------------------------------------------
// Weighted segment pooling.
// ---------------------------------------------------------------------------
__global__ __launch_bounds__(128) void pool_kernel(
    const float* __restrict__ embnew, const float* __restrict__ expP,
    const float* __restrict__ seg, const int* __restrict__ idx,
    float* __restrict__ out)
{
    const int m  = blockIdx.y;
    const int n0 = blockIdx.x * 8;
    const int e  = threadIdx.x;
    const int k  = e >> 5;

    float accum = 0.f;
    int   cur   = -1;
#pragma unroll
    for (int r = 0; r < 8; r++) {
        const int n = n0 + r;
        const int b = idx[n];
        float v = embnew[((long long)m * N_INST + n) * (NATT * DATT) + e];
        v = fmaxf(v, 0.f);
        const float p = expP[((long long)n * NMC + m) * NATT + k] /
                        seg [((long long)b * NMC + m) * NATT + k];
        v *= p;
        if (b != cur) {
            if (cur >= 0) atomicAdd(out + ((long long)cur * NMC + m) * (NATT * DATT) + e, accum);
            cur = b;
            accum = v;
        } else {
            accum += v;
        }
    }
    if (cur >= 0) atomicAdd(out + ((long long)cur * NMC + m) * (NATT * DATT) + e, accum);
}

// ---------------------------------------------------------------------------
__global__ void zero_kernel(float* __restrict__ out, float* __restrict__ seg)
{
    const int i = blockIdx.x * blockDim.x + threadIdx.x;
    if (i < BAGS * NMC * NATT * DATT) out[i] = 0.f;
    if (i < BAGS * NMC * NATT)        seg[i] = 0.f;
}

// ---------------------------------------------------------------------------
extern "C" void kernel_launch(void* const* d_in, const int* in_sizes, int n_in,
                              void* d_out, int out_size)
{
    const float* X      = (const float*)d_in[0];
    const int*   X_idx  = (const int*)  d_in[1];
    const float* Omega1 = (const float*)d_in[2];
    const float* Omega2 = (const float*)d_in[3];
    const float* W1     = (const float*)d_in[4];
    const float* b1     = (const float*)d_in[5];
    const float* W2     = (const float*)d_in[6];
    const float* b2     = (const float*)d_in[7];
    const float* Ws     = (const float*)d_in[8];
    const float* bs     = (const float*)d_in[9];
    const float* Wm     = (const float*)d_in[10];
    const float* bm     = (const float*)d_in[11];
    float* out = (float*)d_out;

    static bool cfg = false;
    if (!cfg) {
        cudaFuncSetAttribute(f16_gemm<1>,
                             cudaFuncAttributeMaxDynamicSharedMemorySize, SMEM_T1);
        cudaFuncSetAttribute(f16_gemm<2>,
                             cudaFuncAttributeMaxDynamicSharedMemorySize, SMEM_T2);
        cfg = true;
    }

    float *z, *expP, *seg;
    __half *Xh, *phih, *h1h, *embh, *embl;
    __half *O1T, *O2T, *W1T, *W2T, *WmT;
    cudaGetSymbolAddress((void**)&z,    g_z);
    cudaGetSymbolAddress((void**)&expP, g_expP);
    cudaGetSymbolAddress((void**)&seg,  g_seg);
    cudaGetSymbolAddress((void**)&Xh,   g_Xh);
    cudaGetSymbolAddress((void**)&phih, g_phih);
    cudaGetSymbolAddress((void**)&h1h,  g_h1h);
    cudaGetSymbolAddress((void**)&embh, g_embh);
    cudaGetSymbolAddress((void**)&embl, g_embl);
    cudaGetSymbolAddress((void**)&O1T,  g_O1T);
    cudaGetSymbolAddress((void**)&O2T,  g_O2T);
    cudaGetSymbolAddress((void**)&W1T,  g_W1T);
    cudaGetSymbolAddress((void**)&W2T,  g_W2T);
    cudaGetSymbolAddress((void**)&WmT,  g_WmT);

    // 1. zero
    zero_kernel<<<128, 256>>>(out, seg);
    // 2. X -> fp16
    {
        long long nX = (long long)N_INST * D0;
        cvt_kernel<<<(unsigned)((nX + 255) / 256), 256>>>(X, Xh, nX);
    }
    // 3. Omega1 transpose (needed by GEMM1)
    splitT_kernel<<<dim3(D0 / 32, RF / 32, NMC), dim3(32, 8)>>>(Omega1, O1T, D0, RF);

    // 4. GEMM1: z1[m] = X @ Omega1[m]   <-- target ncu sample slot
    {
        dim3 g(RF / TBN, N_INST / TBM, NMC);
        f16_gemm<1><<<g, 256, SMEM_T1>>>(
            Xh, nullptr, O1T, nullptr, z, nullptr, nullptr,
            N_INST, RF, D0,
            0LL, (long long)RF * D0, (long long)N_INST * RF);
    }
    // 5-8. remaining weight transposes
    splitT_kernel<<<dim3((2 * RF) / 32, D1 / 32, 1), dim3(32, 8)>>>(W1, W1T, 2 * RF, D1);
    splitT_kernel<<<dim3(D1 / 32, RF / 32, NMC), dim3(32, 8)>>>(Omega2, O2T, D1, RF);
    splitT_kernel<<<dim3((2 * RF) / 32, D2 / 32, 1), dim3(32, 8)>>>(W2, W2T, 2 * RF, D2);
    splitT_kernel<<<dim3(D2 / 32, (NATT * DATT) / 32, 1), dim3(32, 8)>>>(Wm, WmT, D2, NATT * DATT);

    // 9. phi1 = LN(rf(z1))
    rfln_kernel<<<NMC * N_INST, 256>>>(z, phih);

    // 10. h1 = phi1 @ W1 + b1
    {
        dim3 g(D1 / TBN, (NMC * N_INST) / TBM, 1);
        f16_gemm<1><<<g, 256, SMEM_T1>>>(
            phih, nullptr, W1T, b1, nullptr, h1h, nullptr,
            NMC * N_INST, D1, 2 * RF, 0LL, 0LL, 0LL);
    }
    // 11. z2[m] = h1[m] @ Omega2[m]
    {
        dim3 g(RF / TBN, N_INST / TBM, NMC);
        f16_gemm<1><<<g, 256, SMEM_T1>>>(
            h1h, nullptr, O2T, nullptr, z, nullptr, nullptr,
            N_INST, RF, D1,
            (long long)N_INST * D1, (long long)RF * D1, (long long)N_INST * RF);
    }
    // 12. phi2 = LN(rf(z2))
    rfln_kernel<<<NMC * N_INST, 256>>>(z, phih);

    // 13. emb = phi2 @ W2 + b2 -> fp16 hi/lo
    {
        dim3 g(D2 / TBN, (NMC * N_INST) / TBM, 1);
        f16_gemm<1><<<g, 256, SMEM_T1>>>(
            phih, nullptr, W2T, b2, nullptr, embh, embl,
            NMC * N_INST, D2, 2 * RF, 0LL, 0LL, 0LL);
    }
    // 14. attention scores + segment exp-sums
    scores_kernel<<<(NMC * N_INST * 32 + 255) / 256, 256>>>(embh, Ws, bs, X_idx, expP, seg);

    // 15. emb_new = emb @ Wm + bm (2-term A split) -> fp32 z
    {
        dim3 g((NATT * DATT) / TBN, (NMC * N_INST) / TBM, 1);
        f16_gemm<2><<<g, 256, SMEM_T2>>>(
            embh, embl, WmT, bm, z, nullptr, nullptr,
            NMC * N_INST, NATT * DATT, D2, 0LL, 0LL, 0LL);
    }
    // 16. relu + softmax weighting + segment pooling
    pool_kernel<<<dim3(N_INST / 8, NMC), 128>>>(z, expP, seg, X_idx, out);
}

// round 12
// speedup vs baseline: 1.1308x; 1.1308x over previous
#include <cuda_runtime.h>
#include <cuda_fp16.h>
#include <math.h>
#include <stdint.h>

// Problem constants
#define N_INST 16384
#define BAGS   64
#define NMC    4
#define RF     512
#define D0     1024
#define D1     512
#define D2     256
#define NATT   4
#define DATT   32

// ---------------------------------------------------------------------------
// Scratch (static device globals: allocation-guard safe)
// ---------------------------------------------------------------------------
__device__ float g_z   [(size_t)NMC * N_INST * RF];
__device__ float g_expP[(size_t)N_INST * NMC * NATT];
__device__ float g_seg [BAGS * NMC * NATT];

__device__ __half g_Xh  [(size_t)N_INST * D0];
__device__ __half g_phih[(size_t)NMC * N_INST * 2 * RF];
__device__ __half g_h1h [(size_t)NMC * N_INST * D1];
__device__ __half g_embh[(size_t)NMC * N_INST * D2];
__device__ __half g_embl[(size_t)NMC * N_INST * D2];
// fp16 weights, TRANSPOSED [N][K]
__device__ __half g_O1T[(size_t)NMC * RF * D0];
__device__ __half g_O2T[(size_t)NMC * RF * D1];
__device__ __half g_W1T[(size_t)D1 * 2 * RF];
__device__ __half g_W2T[(size_t)D2 * 2 * RF];
__device__ __half g_WmT[(size_t)(NATT * DATT) * D2];

// ---------------------------------------------------------------------------
// Helpers
// ---------------------------------------------------------------------------
__device__ __forceinline__ void h_split(float v, __half& hi, __half& lo) {
    hi = __float2half_rn(v);
    lo = __float2half_rn(v - __half2float(hi));
}

#define CP_ASYNC16(smem_u32, gptr) \
    asm volatile("cp.async.cg.shared.global [%0], [%1], 16;\n" \
                 :: "r"(smem_u32), "l"(gptr))
#define CP_COMMIT()  asm volatile("cp.async.commit_group;\n")
#define CP_WAIT(n)   asm volatile("cp.async.wait_group %0;\n" :: "n"(n))

#define MMA_F16(c, a0, a1, a2, a3, b0, b1) \
    asm volatile("mma.sync.aligned.m16n8k16.row.col.f32.f16.f16.f32 " \
                 "{%0,%1,%2,%3}, {%4,%5,%6,%7}, {%8,%9}, {%0,%1,%2,%3};" \
                 : "+f"((c)[0]), "+f"((c)[1]), "+f"((c)[2]), "+f"((c)[3]) \
                 : "r"(a0), "r"(a1), "r"(a2), "r"(a3), "r"(b0), "r"(b1))

#define LDSM4(r0, r1, r2, r3, addr) \
    asm volatile("ldmatrix.sync.aligned.m8n8.x4.shared.b16 {%0,%1,%2,%3}, [%4];" \
                 : "=r"(r0), "=r"(r1), "=r"(r2), "=r"(r3) : "r"(addr))

// ---------------------------------------------------------------------------
// fp16 tensor-core GEMM, TERMS=1 (pure fp16) or TERMS=2 (A hi/lo split).
// C[M,N] = A[M,K] @ B^T (+bias); B TRANSPOSED [N][K].
// Block tile 128x128x32, 256 threads, warp tile 32x64, 2 CTA/SM.
// 4-buffer cp.async pipeline with a SINGLE __syncthreads per stage
// (NBUF=4 makes the prefetch buffer disjoint from any buffer that a
//  lagging warp can still be reading -> bottom barrier removed).
// ---------------------------------------------------------------------------
#define TBM 128
#define TBN 128
#define TBK 32
#define LDK 40
#define TILE_ELEMS (128 * LDK)
#define NBUF 4

template<int TERMS>
__global__ __launch_bounds__(256, 2) void f16_gemm(
    const __half* __restrict__ Ah, const __half* __restrict__ Al,
    const __half* __restrict__ BhT,
    const float* __restrict__ bias,
    float* __restrict__ C, __half* __restrict__ Chi, __half* __restrict__ Clo,
    int M, int Ncols, int K,
    long long sA, long long sB, long long sC)
{
    constexpr int NT = TERMS + 1;
    constexpr int STAGE_ELEMS = NT * TILE_ELEMS;
    constexpr int B_TILE = TERMS;

    Ah  += (long long)blockIdx.z * sA;
    if (TERMS == 2) Al += (long long)blockIdx.z * sA;
    BhT += (long long)blockIdx.z * sB;
    if (C)   C   += (long long)blockIdx.z * sC;
    if (Chi) Chi += (long long)blockIdx.z * sC;
    if (Clo) Clo += (long long)blockIdx.z * sC;

    extern __shared__ __half smem[];

    const int tid  = threadIdx.x;
    const int wid  = tid >> 5;
    const int lane = tid & 31;
    const int wm   = (wid >> 1) * 32;
    const int wn   = (wid & 1) * 64;
    const int brow = blockIdx.y * TBM;
    const int bcol = blockIdx.x * TBN;
    const int lg   = lane >> 2;
    const int lq2  = (lane & 3) * 2;

    float acc[2][8][4];
#pragma unroll
    for (int mi = 0; mi < 2; mi++)
#pragma unroll
        for (int ni = 0; ni < 8; ni++)
#pragma unroll
            for (int j = 0; j < 4; j++) acc[mi][ni][j] = 0.f;

    const int nStages = K / TBK;
    const uint32_t smemBase = (uint32_t)__cvta_generic_to_shared(smem);

    const int stR = tid >> 1;
    const int stC = (tid & 1) * 16;

    auto stage_cpasync = [&](int buf, int k0) {
        const uint32_t sbb = smemBase + buf * (STAGE_ELEMS * 2);
#pragma unroll
        for (int i = 0; i < 2; i++) {
            const int c = stC + i * 8;
            CP_ASYNC16(sbb + (0 * TILE_ELEMS + stR * LDK + c) * 2,
                       Ah + (long long)(brow + stR) * K + k0 + c);
            if (TERMS == 2)
                CP_ASYNC16(sbb + (1 * TILE_ELEMS + stR * LDK + c) * 2,
                           Al + (long long)(brow + stR) * K + k0 + c);
            CP_ASYNC16(sbb + (B_TILE * TILE_ELEMS + stR * LDK + c) * 2,
                       BhT + (long long)(bcol + stR) * K + k0 + c);
        }
        CP_COMMIT();
    };

    const uint32_t aOff =
        (uint32_t)(((lane & 15) * LDK + (lane >> 4) * 8) * 2);
    const uint32_t bOff =
        (uint32_t)((((lane & 7) + ((lane >> 4) << 3)) * LDK +
                    (((lane >> 3) & 1) << 3)) * 2);

    stage_cpasync(0, 0);
    if (nStages > 1) stage_cpasync(1, TBK);

    for (int s = 0; s < nStages; s++) {
        const int buf = s & 3;
        if (s + 2 < nStages) {
            stage_cpasync((s + 2) & 3, (s + 2) * TBK);
            CP_WAIT(2);
        } else if (s + 1 < nStages) {
            CP_WAIT(1);
        } else {
            CP_WAIT(0);
        }
        __syncthreads();   // single barrier per stage (NBUF=4 hazard-free)

        const uint32_t tb  = smemBase + buf * (STAGE_ELEMS * 2);
        const uint32_t AhB = tb;
        const uint32_t AlB = tb + TILE_ELEMS * 2;
        const uint32_t BhB = tb + B_TILE * TILE_ELEMS * 2;

#pragma unroll
        for (int kk = 0; kk < 2; kk++) {
            const uint32_t kByte = kk * 16 * 2;
            uint32_t ah[2][4], al[2][4];
#pragma unroll
            for (int mi = 0; mi < 2; mi++) {
                const uint32_t rowB = (uint32_t)((wm + mi * 16) * LDK * 2);
                LDSM4(ah[mi][0], ah[mi][1], ah[mi][2], ah[mi][3],
                      AhB + rowB + aOff + kByte);
                if (TERMS == 2)
                    LDSM4(al[mi][0], al[mi][1], al[mi][2], al[mi][3],
                          AlB + rowB + aOff + kByte);
            }
#pragma unroll
            for (int p = 0; p < 4; p++) {
                const uint32_t nB = (uint32_t)((wn + p * 16) * LDK * 2);
                uint32_t bh0, bh1, bh2, bh3;
                LDSM4(bh0, bh1, bh2, bh3, BhB + nB + bOff + kByte);
#pragma unroll
                for (int mi = 0; mi < 2; mi++) {
                    float* c0 = acc[mi][p * 2];
                    float* c1 = acc[mi][p * 2 + 1];
                    MMA_F16(c0, ah[mi][0], ah[mi][1], ah[mi][2], ah[mi][3], bh0, bh1);
                    MMA_F16(c1, ah[mi][0], ah[mi][1], ah[mi][2], ah[mi][3], bh2, bh3);
                    if (TERMS == 2) {
                        MMA_F16(c0, al[mi][0], al[mi][1], al[mi][2], al[mi][3], bh0, bh1);
                        MMA_F16(c1, al[mi][0], al[mi][1], al[mi][2], al[mi][3], bh2, bh3);
                    }
                }
            }
        }
        // no bottom barrier: NBUF=4 keeps prefetch target disjoint
    }

    // Epilogue
#pragma unroll
    for (int mi = 0; mi < 2; mi++) {
        const int row0 = brow + wm + mi * 16 + lg;
#pragma unroll
        for (int ni = 0; ni < 8; ni++) {
            const int col = bcol + wn + ni * 8 + lq2;
            float b0 = 0.f, b1 = 0.f;
            if (bias) { b0 = bias[col]; b1 = bias[col + 1]; }
            float v0 = acc[mi][ni][0] + b0;
            float v1 = acc[mi][ni][1] + b1;
            float v2 = acc[mi][ni][2] + b0;
            float v3 = acc[mi][ni][3] + b1;
            if (C) {
                *(float2*)(C + (long long)row0 * Ncols + col)       = make_float2(v0, v1);
                *(float2*)(C + (long long)(row0 + 8) * Ncols + col) = make_float2(v2, v3);
            }
            if (Chi && !Clo) {
                *(__half2*)(Chi + (long long)row0 * Ncols + col) =
                    __halves2half2(__float2half_rn(v0), __float2half_rn(v1));
                *(__half2*)(Chi + (long long)(row0 + 8) * Ncols + col) =
                    __halves2half2(__float2half_rn(v2), __float2half_rn(v3));
            } else if (Chi) {
                __half h0, l0, h1, l1, h2, l2, h3, l3;
                h_split(v0, h0, l0); h_split(v1, h1, l1);
                h_split(v2, h2, l2); h_split(v3, h3, l3);
                *(__half2*)(Chi + (long long)row0 * Ncols + col)       = __halves2half2(h0, h1);
                *(__half2*)(Clo + (long long)row0 * Ncols + col)       = __halves2half2(l0, l1);
                *(__half2*)(Chi + (long long)(row0 + 8) * Ncols + col) = __halves2half2(h2, h3);
                *(__half2*)(Clo + (long long)(row0 + 8) * Ncols + col) = __halves2half2(l2, l3);
            }
        }
    }
}

#define SMEM_T1 (NBUF * 2 * TILE_ELEMS * 2)   // 81920
#define SMEM_T2 (NBUF * 3 * TILE_ELEMS * 2)   // 122880

// ---------------------------------------------------------------------------
__global__ __launch_bounds__(256) void cvt_kernel(
    const float* __restrict__ src, __half* __restrict__ dst, long long n)
{
    long long i = (long long)blockIdx.x * blockDim.x + threadIdx.x;
    if (i < n) dst[i] = __float2half_rn(src[i]);
}

// fp32 [K][N] -> transposed fp16 [N][K], 32x32 smem-tiled.
__global__ __launch_bounds__(256) void splitT_kernel(
    const float* __restrict__ src, __half* __restrict__ hT, int K, int N)
{
    __shared__ float t[32][33];
    const long long boff = (long long)blockIdx.z * K * N;
    const int k0 = blockIdx.x * 32;
    const int n0 = blockIdx.y * 32;
    const int tx = threadIdx.x, ty = threadIdx.y;

#pragma unroll
    for (int i = 0; i < 32; i += 8)
        t[ty + i][tx] = src[boff + (long long)(k0 + ty + i) * N + n0 + tx];
    __syncthreads();
#pragma unroll
    for (int i = 0; i < 32; i += 8)
        hT[boff + (long long)(n0 + ty + i) * K + k0 + tx] =
            __float2half_rn(t[tx][ty + i]);
}

// ---------------------------------------------------------------------------
// Fused RBF random features + LayerNorm; writes fp16 phi.
// ---------------------------------------------------------------------------
__global__ __launch_bounds__(256) void rfln_kernel(
    const float* __restrict__ z, __half* __restrict__ phih)
{
    const long long row = blockIdx.x;
    const float* zr = z + row * RF;
    __half* ph = phih + row * (2 * RF);
    const int t = threadIdx.x;
    const float scale = 0.044194173824159216f;  // 1/sqrt(512)

    float za = zr[t];
    float zb = zr[t + 256];
    float ca = __cosf(za) * scale;
    float sa = __sinf(za) * scale;
    float cb = __cosf(zb) * scale;
    float sb2 = __sinf(zb) * scale;

    float sum = ca + cb + sa + sb2;
    float sq  = ca * ca + cb * cb + sa * sa + sb2 * sb2;

#pragma unroll
    for (int o = 16; o > 0; o >>= 1) {
        sum += __shfl_down_sync(0xffffffffu, sum, o);
        sq  += __shfl_down_sync(0xffffffffu, sq,  o);
    }
    __shared__ float s_sum[8], s_sq[8];
    __shared__ float s_mean, s_inv;
    const int warp = t >> 5, lane = t & 31;
    if (lane == 0) { s_sum[warp] = sum; s_sq[warp] = sq; }
    __syncthreads();
    if (t == 0) {
        float ts = 0.f, tq = 0.f;
#pragma unroll
        for (int i = 0; i < 8; i++) { ts += s_sum[i]; tq += s_sq[i]; }
        float mean = ts * (1.f / 1024.f);
        float var  = tq * (1.f / 1024.f) - mean * mean;
        s_mean = mean;
        s_inv  = rsqrtf(var + 1e-5f);
    }
    __syncthreads();
    const float mean = s_mean, inv = s_inv;
    ph[t]       = __float2half_rn((ca  - mean) * inv);
    ph[t + 256] = __float2half_rn((cb  - mean) * inv);
    ph[t + 512] = __float2half_rn((sa  - mean) * inv);
    ph[t + 768] = __float2half_rn((sb2 - mean) * inv);
}

// ---------------------------------------------------------------------------
// Attention scores from fp16 emb + per-bag exp-sum (atomics).
// ---------------------------------------------------------------------------
__global__ __launch_bounds__(256) void scores_kernel(
    const __half* __restrict__ embh, const float* __restrict__ Ws,
    const float* __restrict__ bs, const int* __restrict__ idx,
    float* __restrict__ expP, float* __restrict__ seg)
{
    const int gw   = (blockIdx.x * blockDim.x + threadIdx.x) >> 5;
    const int lane = threadIdx.x & 31;
    if (gw >= NMC * N_INST) return;
    const int m = gw / N_INST;
    const int n = gw - m * N_INST;
    const __half2* e = (const __half2*)(embh + (long long)gw * D2);

    float a0 = 0.f, a1 = 0.f, a2 = 0.f, a3 = 0.f;
    for (int d = lane; d < D2 / 2; d += 32) {
        __half2 ev = e[d];
        float e0 = __low2float(ev), e1 = __high2float(ev);
        float4 w0 = *(const float4*)(Ws + (2 * d) * 4);
        float4 w1 = *(const float4*)(Ws + (2 * d + 1) * 4);
        a0 = fmaf(e0, w0.x, fmaf(e1, w1.x, a0));
        a1 = fmaf(e0, w0.y, fmaf(e1, w1.y, a1));
        a2 = fmaf(e0, w0.z, fmaf(e1, w1.z, a2));
        a3 = fmaf(e0, w0.w, fmaf(e1, w1.w, a3));
    }
#pragma unroll
    for (int o = 16; o > 0; o >>= 1) {
        a0 += __shfl_down_sync(0xffffffffu, a0, o);
        a1 += __shfl_down_sync(0xffffffffu, a1, o);
        a2 += __shfl_down_sync(0xffffffffu, a2, o);
        a3 += __shfl_down_sync(0xffffffffu, a3, o);
    }
    if (lane == 0) {
        const int b = idx[n];
        const float inv16 = 0.0625f;
        float v0 = expf((a0 + bs[0]) * inv16);
        float v1 = expf((a1 + bs[1]) * inv16);
        float v2 = expf((a2 + bs[2]) * inv16);
        float v3 = expf((a3 + bs[3]) * inv16);
        float* ep = expP + ((long long)n * NMC + m) * NATT;
        ep[0] = v0; ep[1] = v1; ep[2] = v2; ep[3] = v3;
        float* sp = seg + ((long long)b * NMC + m) * NATT;
        atomicAdd(sp + 0, v0);
        atomicAdd(sp + 1, v1);
        atomicAdd(sp + 2, v2);
        atomicAdd(sp + 3, v3);
    }
}

// ---------------------------------------------------------------------------
// Weighted segment pooling.
// ---------------------------------------------------------------------------
__global__ __launch_bounds__(128) void pool_kernel(
    const float* __restrict__ embnew, const float* __restrict__ expP,
    const float* __restrict__ seg, const int* __restrict__ idx,
    float* __restrict__ out)
{
    const int m  = blockIdx.y;
    const int n0 = blockIdx.x * 8;
    const int e  = threadIdx.x;
    const int k  = e >> 5;

    float accum = 0.f;
    int   cur   = -1;
#pragma unroll
    for (int r = 0; r < 8; r++) {
        const int n = n0 + r;
        const int b = idx[n];
        float v = embnew[((long long)m * N_INST + n) * (NATT * DATT) + e];
        v = fmaxf(v, 0.f);
        const float p = expP[((long long)n * NMC + m) * NATT + k] /
                        seg [((long long)b * NMC + m) * NATT + k];
        v *= p;
        if (b != cur) {
            if (cur >= 0) atomicAdd(out + ((long long)cur * NMC + m) * (NATT * DATT) + e, accum);
            cur = b;
            accum = v;
        } else {
            accum += v;
        }
    }
    if (cur >= 0) atomicAdd(out + ((long long)cur * NMC + m) * (NATT * DATT) + e, accum);
}

// ---------------------------------------------------------------------------
__global__ void zero_kernel(float* __restrict__ out, float* __restrict__ seg)
{
    const int i = blockIdx.x * blockDim.x + threadIdx.x;
    if (i < BAGS * NMC * NATT * DATT) out[i] = 0.f;
    if (i < BAGS * NMC * NATT)        seg[i] = 0.f;
}

// ---------------------------------------------------------------------------
extern "C" void kernel_launch(void* const* d_in, const int* in_sizes, int n_in,
                              void* d_out, int out_size)
{
    const float* X      = (const float*)d_in[0];
    const int*   X_idx  = (const int*)  d_in[1];
    const float* Omega1 = (const float*)d_in[2];
    const float* Omega2 = (const float*)d_in[3];
    const float* W1     = (const float*)d_in[4];
    const float* b1     = (const float*)d_in[5];
    const float* W2     = (const float*)d_in[6];
    const float* b2     = (const float*)d_in[7];
    const float* Ws     = (const float*)d_in[8];
    const float* bs     = (const float*)d_in[9];
    const float* Wm     = (const float*)d_in[10];
    const float* bm     = (const float*)d_in[11];
    float* out = (float*)d_out;

    static bool cfg = false;
    if (!cfg) {
        cudaFuncSetAttribute(f16_gemm<1>,
                             cudaFuncAttributeMaxDynamicSharedMemorySize, SMEM_T1);
        cudaFuncSetAttribute(f16_gemm<2>,
                             cudaFuncAttributeMaxDynamicSharedMemorySize, SMEM_T2);
        cfg = true;
    }

    float *z, *expP, *seg;
    __half *Xh, *phih, *h1h, *embh, *embl;
    __half *O1T, *O2T, *W1T, *W2T, *WmT;
    cudaGetSymbolAddress((void**)&z,    g_z);
    cudaGetSymbolAddress((void**)&expP, g_expP);
    cudaGetSymbolAddress((void**)&seg,  g_seg);
    cudaGetSymbolAddress((void**)&Xh,   g_Xh);
    cudaGetSymbolAddress((void**)&phih, g_phih);
    cudaGetSymbolAddress((void**)&h1h,  g_h1h);
    cudaGetSymbolAddress((void**)&embh, g_embh);
    cudaGetSymbolAddress((void**)&embl, g_embl);
    cudaGetSymbolAddress((void**)&O1T,  g_O1T);
    cudaGetSymbolAddress((void**)&O2T,  g_O2T);
    cudaGetSymbolAddress((void**)&W1T,  g_W1T);
    cudaGetSymbolAddress((void**)&W2T,  g_W2T);
    cudaGetSymbolAddress((void**)&WmT,  g_WmT);

    // 1. zero
    zero_kernel<<<128, 256>>>(out, seg);
    // 2. X -> fp16
    {
        long long nX = (long long)N_INST * D0;
        cvt_kernel<<<(unsigned)((nX + 255) / 256), 256>>>(X, Xh, nX);
    }
    // 3. Omega1 transpose (needed by GEMM1)
    splitT_kernel<<<dim3(D0 / 32, RF / 32, NMC), dim3(32, 8)>>>(Omega1, O1T, D0, RF);

    // 4. GEMM1: z1[m] = X @ Omega1[m]   <-- ncu sample slot
    {
        dim3 g(RF / TBN, N_INST / TBM, NMC);
        f16_gemm<1><<<g, 256, SMEM_T1>>>(
            Xh, nullptr, O1T, nullptr, z, nullptr, nullptr,
            N_INST, RF, D0,
            0LL, (long long)RF * D0, (long long)N_INST * RF);
    }
    // 5-8. remaining weight transposes
    splitT_kernel<<<dim3((2 * RF) / 32, D1 / 32, 1), dim3(32, 8)>>>(W1, W1T, 2 * RF, D1);
    splitT_kernel<<<dim3(D1 / 32, RF / 32, NMC), dim3(32, 8)>>>(Omega2, O2T, D1, RF);
    splitT_kernel<<<dim3((2 * RF) / 32, D2 / 32, 1), dim3(32, 8)>>>(W2, W2T, 2 * RF, D2);
    splitT_kernel<<<dim3(D2 / 32, (NATT * DATT) / 32, 1), dim3(32, 8)>>>(Wm, WmT, D2, NATT * DATT);

    // 9. phi1 = LN(rf(z1))
    rfln_kernel<<<NMC * N_INST, 256>>>(z, phih);

    // 10. h1 = phi1 @ W1 + b1
    {
        dim3 g(D1 / TBN, (NMC * N_INST) / TBM, 1);
        f16_gemm<1><<<g, 256, SMEM_T1>>>(
            phih, nullptr, W1T, b1, nullptr, h1h, nullptr,
            NMC * N_INST, D1, 2 * RF, 0LL, 0LL, 0LL);
    }
    // 11. z2[m] = h1[m] @ Omega2[m]
    {
        dim3 g(RF / TBN, N_INST / TBM, NMC);
        f16_gemm<1><<<g, 256, SMEM_T1>>>(
            h1h, nullptr, O2T, nullptr, z, nullptr, nullptr,
            N_INST, RF, D1,
            (long long)N_INST * D1, (long long)RF * D1, (long long)N_INST * RF);
    }
    // 12. phi2 = LN(rf(z2))
    rfln_kernel<<<NMC * N_INST, 256>>>(z, phih);

    // 13. emb = phi2 @ W2 + b2 -> fp16 hi/lo
    {
        dim3 g(D2 / TBN, (NMC * N_INST) / TBM, 1);
        f16_gemm<1><<<g, 256, SMEM_T1>>>(
            phih, nullptr, W2T, b2, nullptr, embh, embl,
            NMC * N_INST, D2, 2 * RF, 0LL, 0LL, 0LL);
    }
    // 14. attention scores + segment exp-sums
    scores_kernel<<<(NMC * N_INST * 32 + 255) / 256, 256>>>(embh, Ws, bs, X_idx, expP, seg);

    // 15. emb_new = emb @ Wm + bm (2-term A split) -> fp32 z
    {
        dim3 g((NATT * DATT) / TBN, (NMC * N_INST) / TBM, 1);
        f16_gemm<2><<<g, 256, SMEM_T2>>>(
            embh, embl, WmT, bm, z, nullptr, nullptr,
            NMC * N_INST, NATT * DATT, D2, 0LL, 0LL, 0LL);
    }
    // 16. relu + softmax weighting + segment pooling
    pool_kernel<<<dim3(N_INST / 8, NMC), 128>>>(z, expP, seg, X_idx, out);
}

// round 13
// speedup vs baseline: 1.1869x; 1.0497x over previous
#include <cuda_runtime.h>
#include <cuda_fp16.h>
#include <math.h>
#include <stdint.h>

// Problem constants
#define N_INST 16384
#define BAGS   64
#define NMC    4
#define RF     512
#define D0     1024
#define D1     512
#define D2     256
#define NATT   4
#define DATT   32

// ---------------------------------------------------------------------------
// Scratch (static device globals: allocation-guard safe)
// ---------------------------------------------------------------------------
__device__ float g_z   [(size_t)NMC * N_INST * RF];
__device__ float g_expP[(size_t)N_INST * NMC * NATT];
__device__ float g_seg [BAGS * NMC * NATT];

__device__ __half g_Xh  [(size_t)N_INST * D0];
__device__ __half g_phih[(size_t)NMC * N_INST * 2 * RF];
__device__ __half g_h1h [(size_t)NMC * N_INST * D1];
__device__ __half g_embh[(size_t)NMC * N_INST * D2];
// fp16 weights, TRANSPOSED [N][K]
__device__ __half g_O1T[(size_t)NMC * RF * D0];
__device__ __half g_O2T[(size_t)NMC * RF * D1];
__device__ __half g_W1T[(size_t)D1 * 2 * RF];
__device__ __half g_W2T[(size_t)D2 * 2 * RF];
__device__ __half g_WmT[(size_t)(NATT * DATT) * D2];

// ---------------------------------------------------------------------------
#define CP_ASYNC16(smem_u32, gptr) \
    asm volatile("cp.async.cg.shared.global [%0], [%1], 16;\n" \
                 :: "r"(smem_u32), "l"(gptr))
#define CP_COMMIT()  asm volatile("cp.async.commit_group;\n")
#define CP_WAIT(n)   asm volatile("cp.async.wait_group %0;\n" :: "n"(n))

#define MMA_F16(c, a0, a1, a2, a3, b0, b1) \
    asm volatile("mma.sync.aligned.m16n8k16.row.col.f32.f16.f16.f32 " \
                 "{%0,%1,%2,%3}, {%4,%5,%6,%7}, {%8,%9}, {%0,%1,%2,%3};" \
                 : "+f"((c)[0]), "+f"((c)[1]), "+f"((c)[2]), "+f"((c)[3]) \
                 : "r"(a0), "r"(a1), "r"(a2), "r"(a3), "r"(b0), "r"(b1))

#define LDSM4(r0, r1, r2, r3, addr) \
    asm volatile("ldmatrix.sync.aligned.m8n8.x4.shared.b16 {%0,%1,%2,%3}, [%4];" \
                 : "=r"(r0), "=r"(r1), "=r"(r2), "=r"(r3) : "r"(addr))

// ---------------------------------------------------------------------------
// fp16 tensor-core GEMM (single-term). C[M,N] = A[M,K] @ B^T (+bias).
// B TRANSPOSED [N][K]. Block tile 128x128x32, 256 threads, warp tile 32x64,
// 2 CTA/SM, 4-buffer cp.async pipeline with a single __syncthreads/stage.
// POOL=true: fused relu + softmax-weight + segment-sum epilogue (emb_new).
// ---------------------------------------------------------------------------
#define TBM 128
#define TBN 128
#define TBK 32
#define LDK 40
#define TILE_ELEMS (128 * LDK)
#define NBUF 4
#define SMEM_T1 (NBUF * 2 * TILE_ELEMS * 2)   // 81920

template<bool POOL>
__global__ __launch_bounds__(256, 2) void f16_gemm(
    const __half* __restrict__ Ah, const __half* __restrict__ BhT,
    const float* __restrict__ bias,
    float* __restrict__ C, __half* __restrict__ Chi,
    const float* __restrict__ expP, const float* __restrict__ segp,
    const int* __restrict__ idx, float* __restrict__ outp,
    int M, int Ncols, int K,
    long long sA, long long sB, long long sC)
{
    constexpr int STAGE_ELEMS = 2 * TILE_ELEMS;

    Ah  += (long long)blockIdx.z * sA;
    BhT += (long long)blockIdx.z * sB;
    if (C)   C   += (long long)blockIdx.z * sC;
    if (Chi) Chi += (long long)blockIdx.z * sC;

    extern __shared__ __half smem[];

    const int tid  = threadIdx.x;
    const int wid  = tid >> 5;
    const int lane = tid & 31;
    const int wm   = (wid >> 1) * 32;
    const int wn   = (wid & 1) * 64;
    const int brow = blockIdx.y * TBM;
    const int bcol = blockIdx.x * TBN;
    const int lg   = lane >> 2;
    const int lq2  = (lane & 3) * 2;

    float acc[2][8][4];
#pragma unroll
    for (int mi = 0; mi < 2; mi++)
#pragma unroll
        for (int ni = 0; ni < 8; ni++)
#pragma unroll
            for (int j = 0; j < 4; j++) acc[mi][ni][j] = 0.f;

    const int nStages = K / TBK;
    const uint32_t smemBase = (uint32_t)__cvta_generic_to_shared(smem);

    const int stR = tid >> 1;
    const int stC = (tid & 1) * 16;

    auto stage_cpasync = [&](int buf, int k0) {
        const uint32_t sbb = smemBase + buf * (STAGE_ELEMS * 2);
#pragma unroll
        for (int i = 0; i < 2; i++) {
            const int c = stC + i * 8;
            CP_ASYNC16(sbb + (stR * LDK + c) * 2,
                       Ah + (long long)(brow + stR) * K + k0 + c);
            CP_ASYNC16(sbb + (TILE_ELEMS + stR * LDK + c) * 2,
                       BhT + (long long)(bcol + stR) * K + k0 + c);
        }
        CP_COMMIT();
    };

    const uint32_t aOff =
        (uint32_t)(((lane & 15) * LDK + (lane >> 4) * 8) * 2);
    const uint32_t bOff =
        (uint32_t)((((lane & 7) + ((lane >> 4) << 3)) * LDK +
                    (((lane >> 3) & 1) << 3)) * 2);

    stage_cpasync(0, 0);
    if (nStages > 1) stage_cpasync(1, TBK);

    for (int s = 0; s < nStages; s++) {
        const int buf = s & 3;
        if (s + 2 < nStages) {
            stage_cpasync((s + 2) & 3, (s + 2) * TBK);
            CP_WAIT(2);
        } else if (s + 1 < nStages) {
            CP_WAIT(1);
        } else {
            CP_WAIT(0);
        }
        __syncthreads();   // single barrier per stage (NBUF=4 hazard-free)

        const uint32_t tb  = smemBase + buf * (STAGE_ELEMS * 2);
        const uint32_t AhB = tb;
        const uint32_t BhB = tb + TILE_ELEMS * 2;

#pragma unroll
        for (int kk = 0; kk < 2; kk++) {
            const uint32_t kByte = kk * 16 * 2;
            uint32_t ah[2][4];
#pragma unroll
            for (int mi = 0; mi < 2; mi++) {
                const uint32_t rowB = (uint32_t)((wm + mi * 16) * LDK * 2);
                LDSM4(ah[mi][0], ah[mi][1], ah[mi][2], ah[mi][3],
                      AhB + rowB + aOff + kByte);
            }
#pragma unroll
            for (int p = 0; p < 4; p++) {
                const uint32_t nB = (uint32_t)((wn + p * 16) * LDK * 2);
                uint32_t bh0, bh1, bh2, bh3;
                LDSM4(bh0, bh1, bh2, bh3, BhB + nB + bOff + kByte);
#pragma unroll
                for (int mi = 0; mi < 2; mi++) {
                    MMA_F16(acc[mi][p * 2],     ah[mi][0], ah[mi][1], ah[mi][2], ah[mi][3], bh0, bh1);
                    MMA_F16(acc[mi][p * 2 + 1], ah[mi][0], ah[mi][1], ah[mi][2], ah[mi][3], bh2, bh3);
                }
            }
        }
    }

    if (!POOL) {
        // Standard epilogue: fp32 C and/or fp16 Chi
#pragma unroll
        for (int mi = 0; mi < 2; mi++) {
            const int row0 = brow + wm + mi * 16 + lg;
#pragma unroll
            for (int ni = 0; ni < 8; ni++) {
                const int col = bcol + wn + ni * 8 + lq2;
                float b0 = 0.f, b1 = 0.f;
                if (bias) { b0 = bias[col]; b1 = bias[col + 1]; }
                float v0 = acc[mi][ni][0] + b0;
                float v1 = acc[mi][ni][1] + b1;
                float v2 = acc[mi][ni][2] + b0;
                float v3 = acc[mi][ni][3] + b1;
                if (C) {
                    *(float2*)(C + (long long)row0 * Ncols + col)       = make_float2(v0, v1);
                    *(float2*)(C + (long long)(row0 + 8) * Ncols + col) = make_float2(v2, v3);
                }
                if (Chi) {
                    *(__half2*)(Chi + (long long)row0 * Ncols + col) =
                        __halves2half2(__float2half_rn(v0), __float2half_rn(v1));
                    *(__half2*)(Chi + (long long)(row0 + 8) * Ncols + col) =
                        __halves2half2(__float2half_rn(v2), __float2half_rn(v3));
                }
            }
        }
    } else {
        // Fused pooling epilogue (emb_new GEMM):
        // out[b, m, col] += relu(v + bias) * expP[n,m,k]/seg[b,m,k]
        // Thread holds 4 rows: rbase + {0, 8, 16, 24}; same m; bags sorted.
        const int rbase = brow + wm + lg;
        int bags[4], ns[4];
        const int mMC = rbase >> 14;            // rbase / N_INST (same for all 4)
#pragma unroll
        for (int rr = 0; rr < 4; rr++) {
            const int g = rbase + rr * 8;
            ns[rr]   = g & (N_INST - 1);
            bags[rr] = idx[ns[rr]];
        }
#pragma unroll
        for (int ni = 0; ni < 8; ni++) {
            const int col = bcol + wn + ni * 8 + lq2;
            const int k   = col >> 5;           // attention head (DATT=32)
            const float b0 = bias[col];
            const float b1 = bias[col + 1];
            // value layout: [rr][{col, col+1}]
            float v[4][2] = {
                {acc[0][ni][0], acc[0][ni][1]},   // rbase + 0
                {acc[0][ni][2], acc[0][ni][3]},   // rbase + 8
                {acc[1][ni][0], acc[1][ni][1]},   // rbase + 16
                {acc[1][ni][2], acc[1][ni][3]},   // rbase + 24
            };
            float s0 = 0.f, s1 = 0.f;
            int curb = bags[0];
#pragma unroll
            for (int rr = 0; rr < 4; rr++) {
                const float p =
                    expP[(((long long)ns[rr] * NMC) + mMC) * NATT + k] /
                    segp[(((long long)bags[rr] * NMC) + mMC) * NATT + k];
                const float w0 = fmaxf(v[rr][0] + b0, 0.f) * p;
                const float w1 = fmaxf(v[rr][1] + b1, 0.f) * p;
                if (bags[rr] != curb) {
                    float* o = outp + (((long long)curb * NMC) + mMC) * (NATT * DATT) + col;
                    atomicAdd(o,     s0);
                    atomicAdd(o + 1, s1);
                    curb = bags[rr];
                    s0 = 0.f; s1 = 0.f;
                }
                s0 += w0; s1 += w1;
            }
            float* o = outp + (((long long)curb * NMC) + mMC) * (NATT * DATT) + col;
            atomicAdd(o,     s0);
            atomicAdd(o + 1, s1);
        }
    }
}

// ---------------------------------------------------------------------------
__global__ __launch_bounds__(256) void cvt_kernel(
    const float* __restrict__ src, __half* __restrict__ dst, long long n)
{
    long long i = (long long)blockIdx.x * blockDim.x + threadIdx.x;
    if (i < n) dst[i] = __float2half_rn(src[i]);
}

// fp32 [K][N] -> transposed fp16 [N][K], 32x32 smem-tiled.
__global__ __launch_bounds__(256) void splitT_kernel(
    const float* __restrict__ src, __half* __restrict__ hT, int K, int N)
{
    __shared__ float t[32][33];
    const long long boff = (long long)blockIdx.z * K * N;
    const int k0 = blockIdx.x * 32;
    const int n0 = blockIdx.y * 32;
    const int tx = threadIdx.x, ty = threadIdx.y;

#pragma unroll
    for (int i = 0; i < 32; i += 8)
        t[ty + i][tx] = src[boff + (long long)(k0 + ty + i) * N + n0 + tx];
    __syncthreads();
#pragma unroll
    for (int i = 0; i < 32; i += 8)
        hT[boff + (long long)(n0 + ty + i) * K + k0 + tx] =
            __float2half_rn(t[tx][ty + i]);
}

// ---------------------------------------------------------------------------
// Fused RBF random features + LayerNorm; writes fp16 phi.
// ---------------------------------------------------------------------------
__global__ __launch_bounds__(256) void rfln_kernel(
    const float* __restrict__ z, __half* __restrict__ phih)
{
    const long long row = blockIdx.x;
    const float* zr = z + row * RF;
    __half* ph = phih + row * (2 * RF);
    const int t = threadIdx.x;
    const float scale = 0.044194173824159216f;  // 1/sqrt(512)

    float2 z2 = *(const float2*)(zr + 2 * t);   // thread t: elements 2t, 2t+1
    float c0 = __cosf(z2.x) * scale;
    float c1 = __cosf(z2.y) * scale;
    float s0 = __sinf(z2.x) * scale;
    float s1 = __sinf(z2.y) * scale;

    float sum = c0 + c1 + s0 + s1;
    float sq  = c0 * c0 + c1 * c1 + s0 * s0 + s1 * s1;

#pragma unroll
    for (int o = 16; o > 0; o >>= 1) {
        sum += __shfl_down_sync(0xffffffffu, sum, o);
        sq  += __shfl_down_sync(0xffffffffu, sq,  o);
    }
    __shared__ float s_sum[8], s_sq[8];
    __shared__ float s_mean, s_inv;
    const int warp = t >> 5, lane = t & 31;
    if (lane == 0) { s_sum[warp] = sum; s_sq[warp] = sq; }
    __syncthreads();
    if (t == 0) {
        float ts = 0.f, tq = 0.f;
#pragma unroll
        for (int i = 0; i < 8; i++) { ts += s_sum[i]; tq += s_sq[i]; }
        float mean = ts * (1.f / 1024.f);
        float var  = tq * (1.f / 1024.f) - mean * mean;
        s_mean = mean;
        s_inv  = rsqrtf(var + 1e-5f);
    }
    __syncthreads();
    const float mean = s_mean, inv = s_inv;
    // cos features at [0, RF), sin at [RF, 2RF); coalesced __half2 stores
    *(__half2*)(ph + 2 * t) =
        __halves2half2(__float2half_rn((c0 - mean) * inv),
                       __float2half_rn((c1 - mean) * inv));
    *(__half2*)(ph + RF + 2 * t) =
        __halves2half2(__float2half_rn((s0 - mean) * inv),
                       __float2half_rn((s1 - mean) * inv));
}

// ---------------------------------------------------------------------------
// Attention scores from fp16 emb + per-bag exp-sum (atomics).
// ---------------------------------------------------------------------------
__global__ __launch_bounds__(256) void scores_kernel(
    const __half* __restrict__ embh, const float* __restrict__ Ws,
    const float* __restrict__ bs, const int* __restrict__ idx,
    float* __restrict__ expP, float* __restrict__ seg)
{
    const int gw   = (blockIdx.x * blockDim.x + threadIdx.x) >> 5;
    const int lane = threadIdx.x & 31;
    if (gw >= NMC * N_INST) return;
    const int m = gw / N_INST;
    const int n = gw - m * N_INST;
    const __half2* e = (const __half2*)(embh + (long long)gw * D2);

    float a0 = 0.f, a1 = 0.f, a2 = 0.f, a3 = 0.f;
    for (int d = lane; d < D2 / 2; d += 32) {
        __half2 ev = e[d];
        float e0 = __low2float(ev), e1 = __high2float(ev);
        float4 w0 = *(const float4*)(Ws + (2 * d) * 4);
        float4 w1 = *(const float4*)(Ws + (2 * d + 1) * 4);
        a0 = fmaf(e0, w0.x, fmaf(e1, w1.x, a0));
        a1 = fmaf(e0, w0.y, fmaf(e1, w1.y, a1));
        a2 = fmaf(e0, w0.z, fmaf(e1, w1.z, a2));
        a3 = fmaf(e0, w0.w, fmaf(e1, w1.w, a3));
    }
#pragma unroll
    for (int o = 16; o > 0; o >>= 1) {
        a0 += __shfl_down_sync(0xffffffffu, a0, o);
        a1 += __shfl_down_sync(0xffffffffu, a1, o);
        a2 += __shfl_down_sync(0xffffffffu, a2, o);
        a3 += __shfl_down_sync(0xffffffffu, a3, o);
    }
    if (lane == 0) {
        const int b = idx[n];
        const float inv16 = 0.0625f;
        float v0 = expf((a0 + bs[0]) * inv16);
        float v1 = expf((a1 + bs[1]) * inv16);
        float v2 = expf((a2 + bs[2]) * inv16);
        float v3 = expf((a3 + bs[3]) * inv16);
        float* ep = expP + ((long long)n * NMC + m) * NATT;
        ep[0] = v0; ep[1] = v1; ep[2] = v2; ep[3] = v3;
        float* sp = seg + ((long long)b * NMC + m) * NATT;
        atomicAdd(sp + 0, v0);
        atomicAdd(sp + 1, v1);
        atomicAdd(sp + 2, v2);
        atomicAdd(sp + 3, v3);
    }
}

// ---------------------------------------------------------------------------
__global__ void zero_kernel(float* __restrict__ out, float* __restrict__ seg)
{
    const int i = blockIdx.x * blockDim.x + threadIdx.x;
    if (i < BAGS * NMC * NATT * DATT) out[i] = 0.f;
    if (i < BAGS * NMC * NATT)        seg[i] = 0.f;
}

// ---------------------------------------------------------------------------
extern "C" void kernel_launch(void* const* d_in, const int* in_sizes, int n_in,
                              void* d_out, int out_size)
{
    const float* X      = (const float*)d_in[0];
    const int*   X_idx  = (const int*)  d_in[1];
    const float* Omega1 = (const float*)d_in[2];
    const float* Omega2 = (const float*)d_in[3];
    const float* W1     = (const float*)d_in[4];
    const float* b1     = (const float*)d_in[5];
    const float* W2     = (const float*)d_in[6];
    const float* b2     = (const float*)d_in[7];
    const float* Ws     = (const float*)d_in[8];
    const float* bs     = (const float*)d_in[9];
    const float* Wm     = (const float*)d_in[10];
    const float* bm     = (const float*)d_in[11];
    float* out = (float*)d_out;

    static bool cfg = false;
    if (!cfg) {
        cudaFuncSetAttribute(f16_gemm<false>,
                             cudaFuncAttributeMaxDynamicSharedMemorySize, SMEM_T1);
        cudaFuncSetAttribute(f16_gemm<true>,
                             cudaFuncAttributeMaxDynamicSharedMemorySize, SMEM_T1);
        cfg = true;
    }

    float *z, *expP, *seg;
    __half *Xh, *phih, *h1h, *embh;
    __half *O1T, *O2T, *W1T, *W2T, *WmT;
    cudaGetSymbolAddress((void**)&z,    g_z);
    cudaGetSymbolAddress((void**)&expP, g_expP);
    cudaGetSymbolAddress((void**)&seg,  g_seg);
    cudaGetSymbolAddress((void**)&Xh,   g_Xh);
    cudaGetSymbolAddress((void**)&phih, g_phih);
    cudaGetSymbolAddress((void**)&h1h,  g_h1h);
    cudaGetSymbolAddress((void**)&embh, g_embh);
    cudaGetSymbolAddress((void**)&O1T,  g_O1T);
    cudaGetSymbolAddress((void**)&O2T,  g_O2T);
    cudaGetSymbolAddress((void**)&W1T,  g_W1T);
    cudaGetSymbolAddress((void**)&W2T,  g_W2T);
    cudaGetSymbolAddress((void**)&WmT,  g_WmT);

    // 1. Omega1 transpose (needed by GEMM1)
    splitT_kernel<<<dim3(D0 / 32, RF / 32, NMC), dim3(32, 8)>>>(Omega1, O1T, D0, RF);
    // 2. X -> fp16
    {
        long long nX = (long long)N_INST * D0;
        cvt_kernel<<<(unsigned)((nX + 255) / 256), 256>>>(X, Xh, nX);
    }
    // 3. GEMM1: z1[m] = X @ Omega1[m]
    {
        dim3 g(RF / TBN, N_INST / TBM, NMC);
        f16_gemm<false><<<g, 256, SMEM_T1>>>(
            Xh, O1T, nullptr, z, nullptr,
            nullptr, nullptr, nullptr, nullptr,
            N_INST, RF, D0,
            0LL, (long long)RF * D0, (long long)N_INST * RF);
    }
    // 4. phi1 = LN(rf(z1))    <-- ncu sample slot (first rfln profile)
    rfln_kernel<<<NMC * N_INST, 256>>>(z, phih);

    // 5. zero out + seg
    zero_kernel<<<128, 256>>>(out, seg);
    // 6-9. remaining weight transposes
    splitT_kernel<<<dim3((2 * RF) / 32, D1 / 32, 1), dim3(32, 8)>>>(W1, W1T, 2 * RF, D1);
    splitT_kernel<<<dim3(D1 / 32, RF / 32, NMC), dim3(32, 8)>>>(Omega2, O2T, D1, RF);
    splitT_kernel<<<dim3((2 * RF) / 32, D2 / 32, 1), dim3(32, 8)>>>(W2, W2T, 2 * RF, D2);
    splitT_kernel<<<dim3(D2 / 32, (NATT * DATT) / 32, 1), dim3(32, 8)>>>(Wm, WmT, D2, NATT * DATT);

    // 10. h1 = phi1 @ W1 + b1
    {
        dim3 g(D1 / TBN, (NMC * N_INST) / TBM, 1);
        f16_gemm<false><<<g, 256, SMEM_T1>>>(
            phih, W1T, b1, nullptr, h1h,
            nullptr, nullptr, nullptr, nullptr,
            NMC * N_INST, D1, 2 * RF, 0LL, 0LL, 0LL);
    }
    // 11. z2[m] = h1[m] @ Omega2[m]
    {
        dim3 g(RF / TBN, N_INST / TBM, NMC);
        f16_gemm<false><<<g, 256, SMEM_T1>>>(
            h1h, O2T, nullptr, z, nullptr,
            nullptr, nullptr, nullptr, nullptr,
            N_INST, RF, D1,
            (long long)N_INST * D1, (long long)RF * D1, (long long)N_INST * RF);
    }
    // 12. phi2 = LN(rf(z2))
    rfln_kernel<<<NMC * N_INST, 256>>>(z, phih);

    // 13. emb = phi2 @ W2 + b2 -> fp16
    {
        dim3 g(D2 / TBN, (NMC * N_INST) / TBM, 1);
        f16_gemm<false><<<g, 256, SMEM_T1>>>(
            phih, W2T, b2, nullptr, embh,
            nullptr, nullptr, nullptr, nullptr,
            NMC * N_INST, D2, 2 * RF, 0LL, 0LL, 0LL);
    }
    // 14. attention scores + segment exp-sums
    scores_kernel<<<(NMC * N_INST * 32 + 255) / 256, 256>>>(embh, Ws, bs, X_idx, expP, seg);

    // 15. emb_new GEMM with FUSED relu + softmax-weight + segment pooling
    {
        dim3 g((NATT * DATT) / TBN, (NMC * N_INST) / TBM, 1);
        f16_gemm<true><<<g, 256, SMEM_T1>>>(
            embh, WmT, bm, nullptr, nullptr,
            expP, seg, X_idx, out,
            NMC * N_INST, NATT * DATT, D2, 0LL, 0LL, 0LL);
    }
}

// round 14
// speedup vs baseline: 1.2681x; 1.0684x over previous
#include <cuda_runtime.h>
#include <cuda_fp16.h>
#include <math.h>
#include <stdint.h>

// Problem constants
#define N_INST 16384
#define BAGS   64
#define NMC    4
#define RF     512
#define D0     1024
#define D1     512
#define D2     256
#define NATT   4
#define DATT   32

// ---------------------------------------------------------------------------
// Scratch (static device globals: allocation-guard safe)
// ---------------------------------------------------------------------------
__device__ float g_z   [(size_t)NMC * N_INST * RF];
__device__ float g_expP[(size_t)N_INST * NMC * NATT];
__device__ float g_seg [BAGS * NMC * NATT];

__device__ __half g_Xh  [(size_t)N_INST * D0];
__device__ __half g_phih[(size_t)NMC * N_INST * 2 * RF];
__device__ __half g_h1h [(size_t)NMC * N_INST * D1];
__device__ __half g_embh[(size_t)NMC * N_INST * D2];
// fp16 weights, TRANSPOSED [N][K]
__device__ __half g_O1T[(size_t)NMC * RF * D0];
__device__ __half g_O2T[(size_t)NMC * RF * D1];
__device__ __half g_W1T[(size_t)D1 * 2 * RF];
__device__ __half g_W2T[(size_t)D2 * 2 * RF];
__device__ __half g_WmT[(size_t)(NATT * DATT) * D2];

// ---------------------------------------------------------------------------
#define CP_ASYNC16(smem_u32, gptr) \
    asm volatile("cp.async.cg.shared.global [%0], [%1], 16;\n" \
                 :: "r"(smem_u32), "l"(gptr))
#define CP_COMMIT()  asm volatile("cp.async.commit_group;\n")
#define CP_WAIT(n)   asm volatile("cp.async.wait_group %0;\n" :: "n"(n))

#define MMA_F16(c, a0, a1, a2, a3, b0, b1) \
    asm volatile("mma.sync.aligned.m16n8k16.row.col.f32.f16.f16.f32 " \
                 "{%0,%1,%2,%3}, {%4,%5,%6,%7}, {%8,%9}, {%0,%1,%2,%3};" \
                 : "+f"((c)[0]), "+f"((c)[1]), "+f"((c)[2]), "+f"((c)[3]) \
                 : "r"(a0), "r"(a1), "r"(a2), "r"(a3), "r"(b0), "r"(b1))

#define LDSM4(r0, r1, r2, r3, addr) \
    asm volatile("ldmatrix.sync.aligned.m8n8.x4.shared.b16 {%0,%1,%2,%3}, [%4];" \
                 : "=r"(r0), "=r"(r1), "=r"(r2), "=r"(r3) : "r"(addr))

// ---------------------------------------------------------------------------
// fp16 tensor-core GEMM (single-term). C[M,N] = A[M,K] @ B^T (+bias).
// B TRANSPOSED [N][K]. Block tile 128x128x32, 256 threads, warp tile 32x64,
// 2 CTA/SM, 4-buffer cp.async pipeline with a single __syncthreads/stage.
// POOL=true: fused relu + softmax-weight + segment-sum epilogue (emb_new).
// ---------------------------------------------------------------------------
#define TBM 128
#define TBN 128
#define TBK 32
#define LDK 40
#define TILE_ELEMS (128 * LDK)
#define NBUF 4
#define SMEM_T1 (NBUF * 2 * TILE_ELEMS * 2)   // 81920

template<bool POOL>
__global__ __launch_bounds__(256, 2) void f16_gemm(
    const __half* __restrict__ Ah, const __half* __restrict__ BhT,
    const float* __restrict__ bias,
    float* __restrict__ C, __half* __restrict__ Chi,
    const float* __restrict__ expP, const float* __restrict__ segp,
    const int* __restrict__ idx, float* __restrict__ outp,
    int M, int Ncols, int K,
    long long sA, long long sB, long long sC)
{
    constexpr int STAGE_ELEMS = 2 * TILE_ELEMS;

    Ah  += (long long)blockIdx.z * sA;
    BhT += (long long)blockIdx.z * sB;
    if (C)   C   += (long long)blockIdx.z * sC;
    if (Chi) Chi += (long long)blockIdx.z * sC;

    extern __shared__ __half smem[];

    const int tid  = threadIdx.x;
    const int wid  = tid >> 5;
    const int lane = tid & 31;
    const int wm   = (wid >> 1) * 32;
    const int wn   = (wid & 1) * 64;
    const int brow = blockIdx.y * TBM;
    const int bcol = blockIdx.x * TBN;
    const int lg   = lane >> 2;
    const int lq2  = (lane & 3) * 2;

    float acc[2][8][4];
#pragma unroll
    for (int mi = 0; mi < 2; mi++)
#pragma unroll
        for (int ni = 0; ni < 8; ni++)
#pragma unroll
            for (int j = 0; j < 4; j++) acc[mi][ni][j] = 0.f;

    const int nStages = K / TBK;
    const uint32_t smemBase = (uint32_t)__cvta_generic_to_shared(smem);

    const int stR = tid >> 1;
    const int stC = (tid & 1) * 16;

    auto stage_cpasync = [&](int buf, int k0) {
        const uint32_t sbb = smemBase + buf * (STAGE_ELEMS * 2);
#pragma unroll
        for (int i = 0; i < 2; i++) {
            const int c = stC + i * 8;
            CP_ASYNC16(sbb + (stR * LDK + c) * 2,
                       Ah + (long long)(brow + stR) * K + k0 + c);
            CP_ASYNC16(sbb + (TILE_ELEMS + stR * LDK + c) * 2,
                       BhT + (long long)(bcol + stR) * K + k0 + c);
        }
        CP_COMMIT();
    };

    const uint32_t aOff =
        (uint32_t)(((lane & 15) * LDK + (lane >> 4) * 8) * 2);
    const uint32_t bOff =
        (uint32_t)((((lane & 7) + ((lane >> 4) << 3)) * LDK +
                    (((lane >> 3) & 1) << 3)) * 2);

    stage_cpasync(0, 0);
    if (nStages > 1) stage_cpasync(1, TBK);

    for (int s = 0; s < nStages; s++) {
        const int buf = s & 3;
        if (s + 2 < nStages) {
            stage_cpasync((s + 2) & 3, (s + 2) * TBK);
            CP_WAIT(2);
        } else if (s + 1 < nStages) {
            CP_WAIT(1);
        } else {
            CP_WAIT(0);
        }
        __syncthreads();   // single barrier per stage (NBUF=4 hazard-free)

        const uint32_t tb  = smemBase + buf * (STAGE_ELEMS * 2);
        const uint32_t AhB = tb;
        const uint32_t BhB = tb + TILE_ELEMS * 2;

#pragma unroll
        for (int kk = 0; kk < 2; kk++) {
            const uint32_t kByte = kk * 16 * 2;
            uint32_t ah[2][4];
#pragma unroll
            for (int mi = 0; mi < 2; mi++) {
                const uint32_t rowB = (uint32_t)((wm + mi * 16) * LDK * 2);
                LDSM4(ah[mi][0], ah[mi][1], ah[mi][2], ah[mi][3],
                      AhB + rowB + aOff + kByte);
            }
#pragma unroll
            for (int p = 0; p < 4; p++) {
                const uint32_t nB = (uint32_t)((wn + p * 16) * LDK * 2);
                uint32_t bh0, bh1, bh2, bh3;
                LDSM4(bh0, bh1, bh2, bh3, BhB + nB + bOff + kByte);
#pragma unroll
                for (int mi = 0; mi < 2; mi++) {
                    MMA_F16(acc[mi][p * 2],     ah[mi][0], ah[mi][1], ah[mi][2], ah[mi][3], bh0, bh1);
                    MMA_F16(acc[mi][p * 2 + 1], ah[mi][0], ah[mi][1], ah[mi][2], ah[mi][3], bh2, bh3);
                }
            }
        }
    }

    if (!POOL) {
#pragma unroll
        for (int mi = 0; mi < 2; mi++) {
            const int row0 = brow + wm + mi * 16 + lg;
#pragma unroll
            for (int ni = 0; ni < 8; ni++) {
                const int col = bcol + wn + ni * 8 + lq2;
                float b0 = 0.f, b1 = 0.f;
                if (bias) { b0 = bias[col]; b1 = bias[col + 1]; }
                float v0 = acc[mi][ni][0] + b0;
                float v1 = acc[mi][ni][1] + b1;
                float v2 = acc[mi][ni][2] + b0;
                float v3 = acc[mi][ni][3] + b1;
                if (C) {
                    *(float2*)(C + (long long)row0 * Ncols + col)       = make_float2(v0, v1);
                    *(float2*)(C + (long long)(row0 + 8) * Ncols + col) = make_float2(v2, v3);
                }
                if (Chi) {
                    *(__half2*)(Chi + (long long)row0 * Ncols + col) =
                        __halves2half2(__float2half_rn(v0), __float2half_rn(v1));
                    *(__half2*)(Chi + (long long)(row0 + 8) * Ncols + col) =
                        __halves2half2(__float2half_rn(v2), __float2half_rn(v3));
                }
            }
        }
    } else {
        // Fused pooling epilogue (emb_new GEMM):
        // out[b, m, col] += relu(v + bias) * expP[n,m,k]/seg[b,m,k]
        const int rbase = brow + wm + lg;
        int bags[4], ns[4];
        const int mMC = rbase >> 14;            // rbase / N_INST
#pragma unroll
        for (int rr = 0; rr < 4; rr++) {
            const int g = rbase + rr * 8;
            ns[rr]   = g & (N_INST - 1);
            bags[rr] = idx[ns[rr]];
        }
#pragma unroll
        for (int ni = 0; ni < 8; ni++) {
            const int col = bcol + wn + ni * 8 + lq2;
            const int k   = col >> 5;
            const float b0 = bias[col];
            const float b1 = bias[col + 1];
            float v[4][2] = {
                {acc[0][ni][0], acc[0][ni][1]},
                {acc[0][ni][2], acc[0][ni][3]},
                {acc[1][ni][0], acc[1][ni][1]},
                {acc[1][ni][2], acc[1][ni][3]},
            };
            float s0 = 0.f, s1 = 0.f;
            int curb = bags[0];
#pragma unroll
            for (int rr = 0; rr < 4; rr++) {
                const float p =
                    expP[(((long long)ns[rr] * NMC) + mMC) * NATT + k] /
                    segp[(((long long)bags[rr] * NMC) + mMC) * NATT + k];
                const float w0 = fmaxf(v[rr][0] + b0, 0.f) * p;
                const float w1 = fmaxf(v[rr][1] + b1, 0.f) * p;
                if (bags[rr] != curb) {
                    float* o = outp + (((long long)curb * NMC) + mMC) * (NATT * DATT) + col;
                    atomicAdd(o,     s0);
                    atomicAdd(o + 1, s1);
                    curb = bags[rr];
                    s0 = 0.f; s1 = 0.f;
                }
                s0 += w0; s1 += w1;
            }
            float* o = outp + (((long long)curb * NMC) + mMC) * (NATT * DATT) + col;
            atomicAdd(o,     s0);
            atomicAdd(o + 1, s1);
        }
    }
}

// ---------------------------------------------------------------------------
__global__ __launch_bounds__(256) void cvt_kernel(
    const float* __restrict__ src, __half* __restrict__ dst, long long n)
{
    long long i = (long long)blockIdx.x * blockDim.x + threadIdx.x;
    if (i < n) dst[i] = __float2half_rn(src[i]);
}

// fp32 [K][N] -> transposed fp16 [N][K], 32x32 smem-tiled.
__global__ __launch_bounds__(256) void splitT_kernel(
    const float* __restrict__ src, __half* __restrict__ hT, int K, int N)
{
    __shared__ float t[32][33];
    const long long boff = (long long)blockIdx.z * K * N;
    const int k0 = blockIdx.x * 32;
    const int n0 = blockIdx.y * 32;
    const int tx = threadIdx.x, ty = threadIdx.y;

#pragma unroll
    for (int i = 0; i < 32; i += 8)
        t[ty + i][tx] = src[boff + (long long)(k0 + ty + i) * N + n0 + tx];
    __syncthreads();
#pragma unroll
    for (int i = 0; i < 32; i += 8)
        hT[boff + (long long)(n0 + ty + i) * K + k0 + tx] =
            __float2half_rn(t[tx][ty + i]);
}

// ---------------------------------------------------------------------------
// Fused RBF random features + LayerNorm, WARP-PER-ROW.
// Block = 256 threads = 8 warps = 8 rows; lane handles 16 elements.
// No smem, no block barriers: 5-step shfl_xor butterfly reduction.
// ---------------------------------------------------------------------------
__global__ __launch_bounds__(256) void rfln_kernel(
    const float* __restrict__ z, __half* __restrict__ phih)
{
    const int warp = threadIdx.x >> 5;
    const int lane = threadIdx.x & 31;
    const long long row = (long long)blockIdx.x * 8 + warp;

    const float2* z2 = (const float2*)(z + row * RF);
    __half2* ph2 = (__half2*)(phih + row * (2 * RF));
    const float scale = 0.044194173824159216f;  // 1/sqrt(512)

    float c[16], s[16];
    float sum = 0.f, sq = 0.f;
#pragma unroll
    for (int j = 0; j < 8; j++) {
        float2 v = z2[j * 32 + lane];
        float c0 = __cosf(v.x) * scale;
        float c1 = __cosf(v.y) * scale;
        float s0 = __sinf(v.x) * scale;
        float s1 = __sinf(v.y) * scale;
        c[2 * j] = c0; c[2 * j + 1] = c1;
        s[2 * j] = s0; s[2 * j + 1] = s1;
        sum += c0 + c1 + s0 + s1;
        sq  += c0 * c0 + c1 * c1 + s0 * s0 + s1 * s1;
    }
#pragma unroll
    for (int o = 16; o > 0; o >>= 1) {
        sum += __shfl_xor_sync(0xffffffffu, sum, o);
        sq  += __shfl_xor_sync(0xffffffffu, sq,  o);
    }
    const float mean = sum * (1.f / 1024.f);
    const float var  = sq * (1.f / 1024.f) - mean * mean;
    const float inv  = rsqrtf(var + 1e-5f);

#pragma unroll
    for (int j = 0; j < 8; j++) {
        ph2[j * 32 + lane] =
            __halves2half2(__float2half_rn((c[2 * j]     - mean) * inv),
                           __float2half_rn((c[2 * j + 1] - mean) * inv));
        ph2[256 + j * 32 + lane] =
            __halves2half2(__float2half_rn((s[2 * j]     - mean) * inv),
                           __float2half_rn((s[2 * j + 1] - mean) * inv));
    }
}

// ---------------------------------------------------------------------------
// Attention scores from fp16 emb + per-bag exp-sum (atomics).
// ---------------------------------------------------------------------------
__global__ __launch_bounds__(256) void scores_kernel(
    const __half* __restrict__ embh, const float* __restrict__ Ws,
    const float* __restrict__ bs, const int* __restrict__ idx,
    float* __restrict__ expP, float* __restrict__ seg)
{
    const int gw   = (blockIdx.x * blockDim.x + threadIdx.x) >> 5;
    const int lane = threadIdx.x & 31;
    if (gw >= NMC * N_INST) return;
    const int m = gw / N_INST;
    const int n = gw - m * N_INST;
    const __half2* e = (const __half2*)(embh + (long long)gw * D2);

    float a0 = 0.f, a1 = 0.f, a2 = 0.f, a3 = 0.f;
    for (int d = lane; d < D2 / 2; d += 32) {
        __half2 ev = e[d];
        float e0 = __low2float(ev), e1 = __high2float(ev);
        float4 w0 = *(const float4*)(Ws + (2 * d) * 4);
        float4 w1 = *(const float4*)(Ws + (2 * d + 1) * 4);
        a0 = fmaf(e0, w0.x, fmaf(e1, w1.x, a0));
        a1 = fmaf(e0, w0.y, fmaf(e1, w1.y, a1));
        a2 = fmaf(e0, w0.z, fmaf(e1, w1.z, a2));
        a3 = fmaf(e0, w0.w, fmaf(e1, w1.w, a3));
    }
#pragma unroll
    for (int o = 16; o > 0; o >>= 1) {
        a0 += __shfl_down_sync(0xffffffffu, a0, o);
        a1 += __shfl_down_sync(0xffffffffu, a1, o);
        a2 += __shfl_down_sync(0xffffffffu, a2, o);
        a3 += __shfl_down_sync(0xffffffffu, a3, o);
    }
    if (lane == 0) {
        const int b = idx[n];
        const float inv16 = 0.0625f;
        float v0 = expf((a0 + bs[0]) * inv16);
        float v1 = expf((a1 + bs[1]) * inv16);
        float v2 = expf((a2 + bs[2]) * inv16);
        float v3 = expf((a3 + bs[3]) * inv16);
        float* ep = expP + ((long long)n * NMC + m) * NATT;
        ep[0] = v0; ep[1] = v1; ep[2] = v2; ep[3] = v3;
        float* sp = seg + ((long long)b * NMC + m) * NATT;
        atomicAdd(sp + 0, v0);
        atomicAdd(sp + 1, v1);
        atomicAdd(sp + 2, v2);
        atomicAdd(sp + 3, v3);
    }
}

// ---------------------------------------------------------------------------
__global__ void zero_kernel(float* __restrict__ out, float* __restrict__ seg)
{
    const int i = blockIdx.x * blockDim.x + threadIdx.x;
    if (i < BAGS * NMC * NATT * DATT) out[i] = 0.f;
    if (i < BAGS * NMC * NATT)        seg[i] = 0.f;
}

// ---------------------------------------------------------------------------
extern "C" void kernel_launch(void* const* d_in, const int* in_sizes, int n_in,
                              void* d_out, int out_size)
{
    const float* X      = (const float*)d_in[0];
    const int*   X_idx  = (const int*)  d_in[1];
    const float* Omega1 = (const float*)d_in[2];
    const float* Omega2 = (const float*)d_in[3];
    const float* W1     = (const float*)d_in[4];
    const float* b1     = (const float*)d_in[5];
    const float* W2     = (const float*)d_in[6];
    const float* b2     = (const float*)d_in[7];
    const float* Ws     = (const float*)d_in[8];
    const float* bs     = (const float*)d_in[9];
    const float* Wm     = (const float*)d_in[10];
    const float* bm     = (const float*)d_in[11];
    float* out = (float*)d_out;

    static bool cfg = false;
    if (!cfg) {
        cudaFuncSetAttribute(f16_gemm<false>,
                             cudaFuncAttributeMaxDynamicSharedMemorySize, SMEM_T1);
        cudaFuncSetAttribute(f16_gemm<true>,
                             cudaFuncAttributeMaxDynamicSharedMemorySize, SMEM_T1);
        cfg = true;
    }

    float *z, *expP, *seg;
    __half *Xh, *phih, *h1h, *embh;
    __half *O1T, *O2T, *W1T, *W2T, *WmT;
    cudaGetSymbolAddress((void**)&z,    g_z);
    cudaGetSymbolAddress((void**)&expP, g_expP);
    cudaGetSymbolAddress((void**)&seg,  g_seg);
    cudaGetSymbolAddress((void**)&Xh,   g_Xh);
    cudaGetSymbolAddress((void**)&phih, g_phih);
    cudaGetSymbolAddress((void**)&h1h,  g_h1h);
    cudaGetSymbolAddress((void**)&embh, g_embh);
    cudaGetSymbolAddress((void**)&O1T,  g_O1T);
    cudaGetSymbolAddress((void**)&O2T,  g_O2T);
    cudaGetSymbolAddress((void**)&W1T,  g_W1T);
    cudaGetSymbolAddress((void**)&W2T,  g_W2T);
    cudaGetSymbolAddress((void**)&WmT,  g_WmT);

    // 1. Omega1 transpose (needed by GEMM1)
    splitT_kernel<<<dim3(D0 / 32, RF / 32, NMC), dim3(32, 8)>>>(Omega1, O1T, D0, RF);
    // 2. X -> fp16
    {
        long long nX = (long long)N_INST * D0;
        cvt_kernel<<<(unsigned)((nX + 255) / 256), 256>>>(X, Xh, nX);
    }
    // 3. GEMM1: z1[m] = X @ Omega1[m]
    {
        dim3 g(RF / TBN, N_INST / TBM, NMC);
        f16_gemm<false><<<g, 256, SMEM_T1>>>(
            Xh, O1T, nullptr, z, nullptr,
            nullptr, nullptr, nullptr, nullptr,
            N_INST, RF, D0,
            0LL, (long long)RF * D0, (long long)N_INST * RF);
    }
    // 4. phi1 = LN(rf(z1))    <-- ncu sample slot (verify warp-per-row win)
    rfln_kernel<<<(NMC * N_INST) / 8, 256>>>(z, phih);

    // 5. zero out + seg
    zero_kernel<<<128, 256>>>(out, seg);
    // 6-9. remaining weight transposes
    splitT_kernel<<<dim3((2 * RF) / 32, D1 / 32, 1), dim3(32, 8)>>>(W1, W1T, 2 * RF, D1);
    splitT_kernel<<<dim3(D1 / 32, RF / 32, NMC), dim3(32, 8)>>>(Omega2, O2T, D1, RF);
    splitT_kernel<<<dim3((2 * RF) / 32, D2 / 32, 1), dim3(32, 8)>>>(W2, W2T, 2 * RF, D2);
    splitT_kernel<<<dim3(D2 / 32, (NATT * DATT) / 32, 1), dim3(32, 8)>>>(Wm, WmT, D2, NATT * DATT);

    // 10. h1 = phi1 @ W1 + b1
    {
        dim3 g(D1 / TBN, (NMC * N_INST) / TBM, 1);
        f16_gemm<false><<<g, 256, SMEM_T1>>>(
            phih, W1T, b1, nullptr, h1h,
            nullptr, nullptr, nullptr, nullptr,
            NMC * N_INST, D1, 2 * RF, 0LL, 0LL, 0LL);
    }
    // 11. z2[m] = h1[m] @ Omega2[m]
    {
        dim3 g(RF / TBN, N_INST / TBM, NMC);
        f16_gemm<false><<<g, 256, SMEM_T1>>>(
            h1h, O2T, nullptr, z, nullptr,
            nullptr, nullptr, nullptr, nullptr,
            N_INST, RF, D1,
            (long long)N_INST * D1, (long long)RF * D1, (long long)N_INST * RF);
    }
    // 12. phi2 = LN(rf(z2))
    rfln_kernel<<<(NMC * N_INST) / 8, 256>>>(z, phih);

    // 13. emb = phi2 @ W2 + b2 -> fp16
    {
        dim3 g(D2 / TBN, (NMC * N_INST) / TBM, 1);
        f16_gemm<false><<<g, 256, SMEM_T1>>>(
            phih, W2T, b2, nullptr, embh,
            nullptr, nullptr, nullptr, nullptr,
            NMC * N_INST, D2, 2 * RF, 0LL, 0LL, 0LL);
    }
    // 14. attention scores + segment exp-sums
    scores_kernel<<<(NMC * N_INST * 32 + 255) / 256, 256>>>(embh, Ws, bs, X_idx, expP, seg);

    // 15. emb_new GEMM with FUSED relu + softmax-weight + segment pooling
    {
        dim3 g((NATT * DATT) / TBN, (NMC * N_INST) / TBM, 1);
        f16_gemm<true><<<g, 256, SMEM_T1>>>(
            embh, WmT, bm, nullptr, nullptr,
            expP, seg, X_idx, out,
            NMC * N_INST, NATT * DATT, D2, 0LL, 0LL, 0LL);
    }
}

// round 15
// speedup vs baseline: 1.4663x; 1.1563x over previous
#include <cuda_runtime.h>
#include <cuda_fp16.h>
#include <math.h>
#include <stdint.h>

// Problem constants
#define N_INST 16384
#define BAGS   64
#define NMC    4
#define RF     512
#define D0     1024
#define D1     512
#define D2     256
#define NATT   4
#define DATT   32

// ---------------------------------------------------------------------------
// Scratch (static device globals: allocation-guard safe)
// ---------------------------------------------------------------------------
__device__ float g_expP[(size_t)N_INST * NMC * NATT];
__device__ float g_seg [BAGS * NMC * NATT];
__device__ float g_bias2[NMC * RF];

__device__ __half g_Xh  [(size_t)N_INST * D0];
__device__ __half g_zh  [(size_t)NMC * N_INST * RF];      // z1 / z2 (fp16)
__device__ __half g_phih[(size_t)NMC * N_INST * 2 * RF];
__device__ __half g_embh[(size_t)NMC * N_INST * D2];
// fp16 weights
__device__ __half g_O1T [(size_t)NMC * RF * D0];           // [r][d0] transposed
__device__ __half g_O2T [(size_t)NMC * RF * D1];           // [r][d1] transposed
__device__ __half g_W1h [(size_t)(2 * RF) * D1];           // W1 row-major [f][d1]
__device__ __half g_W12T[(size_t)NMC * RF * 2 * RF];       // (W1@O2)^T [r][f]
__device__ __half g_W2T [(size_t)D2 * 2 * RF];
__device__ __half g_WmT [(size_t)(NATT * DATT) * D2];

// ---------------------------------------------------------------------------
#define CP_ASYNC16(smem_u32, gptr) \
    asm volatile("cp.async.cg.shared.global [%0], [%1], 16;\n" \
                 :: "r"(smem_u32), "l"(gptr))
#define CP_COMMIT()  asm volatile("cp.async.commit_group;\n")
#define CP_WAIT(n)   asm volatile("cp.async.wait_group %0;\n" :: "n"(n))

#define MMA_F16(c, a0, a1, a2, a3, b0, b1) \
    asm volatile("mma.sync.aligned.m16n8k16.row.col.f32.f16.f16.f32 " \
                 "{%0,%1,%2,%3}, {%4,%5,%6,%7}, {%8,%9}, {%0,%1,%2,%3};" \
                 : "+f"((c)[0]), "+f"((c)[1]), "+f"((c)[2]), "+f"((c)[3]) \
                 : "r"(a0), "r"(a1), "r"(a2), "r"(a3), "r"(b0), "r"(b1))

#define LDSM4(r0, r1, r2, r3, addr) \
    asm volatile("ldmatrix.sync.aligned.m8n8.x4.shared.b16 {%0,%1,%2,%3}, [%4];" \
                 : "=r"(r0), "=r"(r1), "=r"(r2), "=r"(r3) : "r"(addr))

// ---------------------------------------------------------------------------
// fp16 tensor-core GEMM. C[M,N] = A[M,K] @ B^T (+bias); B TRANSPOSED [N][K].
// Block tile 128x128x32, 256 threads, warp tile 32x64, 2 CTA/SM,
// 4-buffer cp.async pipeline, single __syncthreads per stage.
// POOL=true: fused relu + softmax-weight + segment-sum epilogue.
// ---------------------------------------------------------------------------
#define TBM 128
#define TBN 128
#define TBK 32
#define LDK 40
#define TILE_ELEMS (128 * LDK)
#define NBUF 4
#define SMEM_T1 (NBUF * 2 * TILE_ELEMS * 2)   // 81920

template<bool POOL>
__global__ __launch_bounds__(256, 2) void f16_gemm(
    const __half* __restrict__ Ah, const __half* __restrict__ BhT,
    const float* __restrict__ bias,
    float* __restrict__ C, __half* __restrict__ Chi,
    const float* __restrict__ expP, const float* __restrict__ segp,
    const int* __restrict__ idx, float* __restrict__ outp,
    int M, int Ncols, int K,
    long long sA, long long sB, long long sC, long long sBias)
{
    constexpr int STAGE_ELEMS = 2 * TILE_ELEMS;

    Ah  += (long long)blockIdx.z * sA;
    BhT += (long long)blockIdx.z * sB;
    if (C)    C    += (long long)blockIdx.z * sC;
    if (Chi)  Chi  += (long long)blockIdx.z * sC;
    if (bias) bias += (long long)blockIdx.z * sBias;

    extern __shared__ __half smem[];

    const int tid  = threadIdx.x;
    const int wid  = tid >> 5;
    const int lane = tid & 31;
    const int wm   = (wid >> 1) * 32;
    const int wn   = (wid & 1) * 64;
    const int brow = blockIdx.y * TBM;
    const int bcol = blockIdx.x * TBN;
    const int lg   = lane >> 2;
    const int lq2  = (lane & 3) * 2;

    float acc[2][8][4];
#pragma unroll
    for (int mi = 0; mi < 2; mi++)
#pragma unroll
        for (int ni = 0; ni < 8; ni++)
#pragma unroll
            for (int j = 0; j < 4; j++) acc[mi][ni][j] = 0.f;

    const int nStages = K / TBK;
    const uint32_t smemBase = (uint32_t)__cvta_generic_to_shared(smem);

    const int stR = tid >> 1;
    const int stC = (tid & 1) * 16;

    auto stage_cpasync = [&](int buf, int k0) {
        const uint32_t sbb = smemBase + buf * (STAGE_ELEMS * 2);
#pragma unroll
        for (int i = 0; i < 2; i++) {
            const int c = stC + i * 8;
            CP_ASYNC16(sbb + (stR * LDK + c) * 2,
                       Ah + (long long)(brow + stR) * K + k0 + c);
            CP_ASYNC16(sbb + (TILE_ELEMS + stR * LDK + c) * 2,
                       BhT + (long long)(bcol + stR) * K + k0 + c);
        }
        CP_COMMIT();
    };

    const uint32_t aOff =
        (uint32_t)(((lane & 15) * LDK + (lane >> 4) * 8) * 2);
    const uint32_t bOff =
        (uint32_t)((((lane & 7) + ((lane >> 4) << 3)) * LDK +
                    (((lane >> 3) & 1) << 3)) * 2);

    stage_cpasync(0, 0);
    if (nStages > 1) stage_cpasync(1, TBK);

    for (int s = 0; s < nStages; s++) {
        const int buf = s & 3;
        if (s + 2 < nStages) {
            stage_cpasync((s + 2) & 3, (s + 2) * TBK);
            CP_WAIT(2);
        } else if (s + 1 < nStages) {
            CP_WAIT(1);
        } else {
            CP_WAIT(0);
        }
        __syncthreads();   // single barrier per stage (NBUF=4 hazard-free)

        const uint32_t tb  = smemBase + buf * (STAGE_ELEMS * 2);
        const uint32_t AhB = tb;
        const uint32_t BhB = tb + TILE_ELEMS * 2;

#pragma unroll
        for (int kk = 0; kk < 2; kk++) {
            const uint32_t kByte = kk * 16 * 2;
            uint32_t ah[2][4];
#pragma unroll
            for (int mi = 0; mi < 2; mi++) {
                const uint32_t rowB = (uint32_t)((wm + mi * 16) * LDK * 2);
                LDSM4(ah[mi][0], ah[mi][1], ah[mi][2], ah[mi][3],
                      AhB + rowB + aOff + kByte);
            }
#pragma unroll
            for (int p = 0; p < 4; p++) {
                const uint32_t nB = (uint32_t)((wn + p * 16) * LDK * 2);
                uint32_t bh0, bh1, bh2, bh3;
                LDSM4(bh0, bh1, bh2, bh3, BhB + nB + bOff + kByte);
#pragma unroll
                for (int mi = 0; mi < 2; mi++) {
                    MMA_F16(acc[mi][p * 2],     ah[mi][0], ah[mi][1], ah[mi][2], ah[mi][3], bh0, bh1);
                    MMA_F16(acc[mi][p * 2 + 1], ah[mi][0], ah[mi][1], ah[mi][2], ah[mi][3], bh2, bh3);
                }
            }
        }
    }

    if (!POOL) {
#pragma unroll
        for (int mi = 0; mi < 2; mi++) {
            const int row0 = brow + wm + mi * 16 + lg;
#pragma unroll
            for (int ni = 0; ni < 8; ni++) {
                const int col = bcol + wn + ni * 8 + lq2;
                float b0 = 0.f, b1 = 0.f;
                if (bias) { b0 = bias[col]; b1 = bias[col + 1]; }
                float v0 = acc[mi][ni][0] + b0;
                float v1 = acc[mi][ni][1] + b1;
                float v2 = acc[mi][ni][2] + b0;
                float v3 = acc[mi][ni][3] + b1;
                if (C) {
                    *(float2*)(C + (long long)row0 * Ncols + col)       = make_float2(v0, v1);
                    *(float2*)(C + (long long)(row0 + 8) * Ncols + col) = make_float2(v2, v3);
                }
                if (Chi) {
                    *(__half2*)(Chi + (long long)row0 * Ncols + col) =
                        __halves2half2(__float2half_rn(v0), __float2half_rn(v1));
                    *(__half2*)(Chi + (long long)(row0 + 8) * Ncols + col) =
                        __halves2half2(__float2half_rn(v2), __float2half_rn(v3));
                }
            }
        }
    } else {
        // Fused pooling epilogue (emb_new GEMM)
        const int rbase = brow + wm + lg;
        int bags[4], ns[4];
        const int mMC = rbase >> 14;            // rbase / N_INST
#pragma unroll
        for (int rr = 0; rr < 4; rr++) {
            const int g = rbase + rr * 8;
            ns[rr]   = g & (N_INST - 1);
            bags[rr] = idx[ns[rr]];
        }
#pragma unroll
        for (int ni = 0; ni < 8; ni++) {
            const int col = bcol + wn + ni * 8 + lq2;
            const int k   = col >> 5;
            const float b0 = bias[col];
            const float b1 = bias[col + 1];
            float v[4][2] = {
                {acc[0][ni][0], acc[0][ni][1]},
                {acc[0][ni][2], acc[0][ni][3]},
                {acc[1][ni][0], acc[1][ni][1]},
                {acc[1][ni][2], acc[1][ni][3]},
            };
            float s0 = 0.f, s1 = 0.f;
            int curb = bags[0];
#pragma unroll
            for (int rr = 0; rr < 4; rr++) {
                const float p =
                    expP[(((long long)ns[rr] * NMC) + mMC) * NATT + k] /
                    segp[(((long long)bags[rr] * NMC) + mMC) * NATT + k];
                const float w0 = fmaxf(v[rr][0] + b0, 0.f) * p;
                const float w1 = fmaxf(v[rr][1] + b1, 0.f) * p;
                if (bags[rr] != curb) {
                    float* o = outp + (((long long)curb * NMC) + mMC) * (NATT * DATT) + col;
                    atomicAdd(o,     s0);
                    atomicAdd(o + 1, s1);
                    curb = bags[rr];
                    s0 = 0.f; s1 = 0.f;
                }
                s0 += w0; s1 += w1;
            }
            float* o = outp + (((long long)curb * NMC) + mMC) * (NATT * DATT) + col;
            atomicAdd(o,     s0);
            atomicAdd(o + 1, s1);
        }
    }
}

// ---------------------------------------------------------------------------
__global__ __launch_bounds__(256) void cvt_kernel(
    const float* __restrict__ src, __half* __restrict__ dst, long long n)
{
    long long i = (long long)blockIdx.x * blockDim.x + threadIdx.x;
    if (i < n) dst[i] = __float2half_rn(src[i]);
}

// fp32 [K][N] -> transposed fp16 [N][K], 32x32 smem-tiled.
__global__ __launch_bounds__(256) void splitT_kernel(
    const float* __restrict__ src, __half* __restrict__ hT, int K, int N)
{
    __shared__ float t[32][33];
    const long long boff = (long long)blockIdx.z * K * N;
    const int k0 = blockIdx.x * 32;
    const int n0 = blockIdx.y * 32;
    const int tx = threadIdx.x, ty = threadIdx.y;

#pragma unroll
    for (int i = 0; i < 32; i += 8)
        t[ty + i][tx] = src[boff + (long long)(k0 + ty + i) * N + n0 + tx];
    __syncthreads();
#pragma unroll
    for (int i = 0; i < 32; i += 8)
        hT[boff + (long long)(n0 + ty + i) * K + k0 + tx] =
            __float2half_rn(t[tx][ty + i]);
}

// ---------------------------------------------------------------------------
// bias2[m][r] = sum_d b1[d] * O2T[m][r][d]   (one warp per (m, r))
// ---------------------------------------------------------------------------
__global__ __launch_bounds__(256) void bias2_kernel(
    const float* __restrict__ b1, const __half* __restrict__ O2T,
    float* __restrict__ bias2)
{
    const int warp = threadIdx.x >> 5;
    const int lane = threadIdx.x & 31;
    const int r = blockIdx.x * 8 + warp;     // 0..511
    const int m = blockIdx.y;
    const __half* row = O2T + ((long long)m * RF + r) * D1;
    float s = 0.f;
    for (int d = lane; d < D1; d += 32)
        s = fmaf(__half2float(row[d]), b1[d], s);
#pragma unroll
    for (int o = 16; o > 0; o >>= 1)
        s += __shfl_xor_sync(0xffffffffu, s, o);
    if (lane == 0) bias2[m * RF + r] = s;
}

// ---------------------------------------------------------------------------
// Fused RBF random features + LayerNorm, warp-per-row, fp16 z input.
// ---------------------------------------------------------------------------
__global__ __launch_bounds__(256) void rfln_kernel(
    const __half* __restrict__ z, __half* __restrict__ phih)
{
    const int warp = threadIdx.x >> 5;
    const int lane = threadIdx.x & 31;
    const long long row = (long long)blockIdx.x * 8 + warp;

    const __half2* z2 = (const __half2*)(z + row * RF);
    __half2* ph2 = (__half2*)(phih + row * (2 * RF));
    const float scale = 0.044194173824159216f;  // 1/sqrt(512)

    float c[16], s[16];
    float sum = 0.f, sq = 0.f;
#pragma unroll
    for (int j = 0; j < 8; j++) {
        __half2 v = z2[j * 32 + lane];
        float vx = __low2float(v), vy = __high2float(v);
        float c0 = __cosf(vx) * scale;
        float c1 = __cosf(vy) * scale;
        float s0 = __sinf(vx) * scale;
        float s1 = __sinf(vy) * scale;
        c[2 * j] = c0; c[2 * j + 1] = c1;
        s[2 * j] = s0; s[2 * j + 1] = s1;
        sum += c0 + c1 + s0 + s1;
        sq  += c0 * c0 + c1 * c1 + s0 * s0 + s1 * s1;
    }
#pragma unroll
    for (int o = 16; o > 0; o >>= 1) {
        sum += __shfl_xor_sync(0xffffffffu, sum, o);
        sq  += __shfl_xor_sync(0xffffffffu, sq,  o);
    }
    const float mean = sum * (1.f / 1024.f);
    const float var  = sq * (1.f / 1024.f) - mean * mean;
    const float inv  = rsqrtf(var + 1e-5f);

#pragma unroll
    for (int j = 0; j < 8; j++) {
        ph2[j * 32 + lane] =
            __halves2half2(__float2half_rn((c[2 * j]     - mean) * inv),
                           __float2half_rn((c[2 * j + 1] - mean) * inv));
        ph2[256 + j * 32 + lane] =
            __halves2half2(__float2half_rn((s[2 * j]     - mean) * inv),
                           __float2half_rn((s[2 * j + 1] - mean) * inv));
    }
}

// ---------------------------------------------------------------------------
// Attention scores from fp16 emb + per-bag exp-sum (atomics).
// ---------------------------------------------------------------------------
__global__ __launch_bounds__(256) void scores_kernel(
    const __half* __restrict__ embh, const float* __restrict__ Ws,
    const float* __restrict__ bs, const int* __restrict__ idx,
    float* __restrict__ expP, float* __restrict__ seg)
{
    const int gw   = (blockIdx.x * blockDim.x + threadIdx.x) >> 5;
    const int lane = threadIdx.x & 31;
    if (gw >= NMC * N_INST) return;
    const int m = gw / N_INST;
    const int n = gw - m * N_INST;
    const __half2* e = (const __half2*)(embh + (long long)gw * D2);

    float a0 = 0.f, a1 = 0.f, a2 = 0.f, a3 = 0.f;
    for (int d = lane; d < D2 / 2; d += 32) {
        __half2 ev = e[d];
        float e0 = __low2float(ev), e1 = __high2float(ev);
        float4 w0 = *(const float4*)(Ws + (2 * d) * 4);
        float4 w1 = *(const float4*)(Ws + (2 * d + 1) * 4);
        a0 = fmaf(e0, w0.x, fmaf(e1, w1.x, a0));
        a1 = fmaf(e0, w0.y, fmaf(e1, w1.y, a1));
        a2 = fmaf(e0, w0.z, fmaf(e1, w1.z, a2));
        a3 = fmaf(e0, w0.w, fmaf(e1, w1.w, a3));
    }
#pragma unroll
    for (int o = 16; o > 0; o >>= 1) {
        a0 += __shfl_down_sync(0xffffffffu, a0, o);
        a1 += __shfl_down_sync(0xffffffffu, a1, o);
        a2 += __shfl_down_sync(0xffffffffu, a2, o);
        a3 += __shfl_down_sync(0xffffffffu, a3, o);
    }
    if (lane == 0) {
        const int b = idx[n];
        const float inv16 = 0.0625f;
        float v0 = expf((a0 + bs[0]) * inv16);
        float v1 = expf((a1 + bs[1]) * inv16);
        float v2 = expf((a2 + bs[2]) * inv16);
        float v3 = expf((a3 + bs[3]) * inv16);
        float* ep = expP + ((long long)n * NMC + m) * NATT;
        ep[0] = v0; ep[1] = v1; ep[2] = v2; ep[3] = v3;
        float* sp = seg + ((long long)b * NMC + m) * NATT;
        atomicAdd(sp + 0, v0);
        atomicAdd(sp + 1, v1);
        atomicAdd(sp + 2, v2);
        atomicAdd(sp + 3, v3);
    }
}

// ---------------------------------------------------------------------------
__global__ void zero_kernel(float* __restrict__ out, float* __restrict__ seg)
{
    const int i = blockIdx.x * blockDim.x + threadIdx.x;
    if (i < BAGS * NMC * NATT * DATT) out[i] = 0.f;
    if (i < BAGS * NMC * NATT)        seg[i] = 0.f;
}

// ---------------------------------------------------------------------------
extern "C" void kernel_launch(void* const* d_in, const int* in_sizes, int n_in,
                              void* d_out, int out_size)
{
    const float* X      = (const float*)d_in[0];
    const int*   X_idx  = (const int*)  d_in[1];
    const float* Omega1 = (const float*)d_in[2];
    const float* Omega2 = (const float*)d_in[3];
    const float* W1     = (const float*)d_in[4];
    const float* b1     = (const float*)d_in[5];
    const float* W2     = (const float*)d_in[6];
    const float* b2     = (const float*)d_in[7];
    const float* Ws     = (const float*)d_in[8];
    const float* bs     = (const float*)d_in[9];
    const float* Wm     = (const float*)d_in[10];
    const float* bm     = (const float*)d_in[11];
    float* out = (float*)d_out;

    static bool cfg = false;
    if (!cfg) {
        cudaFuncSetAttribute(f16_gemm<false>,
                             cudaFuncAttributeMaxDynamicSharedMemorySize, SMEM_T1);
        cudaFuncSetAttribute(f16_gemm<true>,
                             cudaFuncAttributeMaxDynamicSharedMemorySize, SMEM_T1);
        cfg = true;
    }

    float *expP, *seg, *bias2;
    __half *Xh, *zh, *phih, *embh;
    __half *O1T, *O2T, *W1h, *W12T, *W2T, *WmT;
    cudaGetSymbolAddress((void**)&expP,  g_expP);
    cudaGetSymbolAddress((void**)&seg,   g_seg);
    cudaGetSymbolAddress((void**)&bias2, g_bias2);
    cudaGetSymbolAddress((void**)&Xh,    g_Xh);
    cudaGetSymbolAddress((void**)&zh,    g_zh);
    cudaGetSymbolAddress((void**)&phih,  g_phih);
    cudaGetSymbolAddress((void**)&embh,  g_embh);
    cudaGetSymbolAddress((void**)&O1T,   g_O1T);
    cudaGetSymbolAddress((void**)&O2T,   g_O2T);
    cudaGetSymbolAddress((void**)&W1h,   g_W1h);
    cudaGetSymbolAddress((void**)&W12T,  g_W12T);
    cudaGetSymbolAddress((void**)&W2T,   g_W2T);
    cudaGetSymbolAddress((void**)&WmT,   g_WmT);

    // 1. Omega1 transpose (needed by GEMM1)
    splitT_kernel<<<dim3(D0 / 32, RF / 32, NMC), dim3(32, 8)>>>(Omega1, O1T, D0, RF);
    // 2. X -> fp16
    {
        long long nX = (long long)N_INST * D0;
        cvt_kernel<<<(unsigned)((nX + 255) / 256), 256>>>(X, Xh, nX);
    }
    // 3. GEMM1: z1[m] = X @ Omega1[m] -> fp16 zh
    {
        dim3 g(RF / TBN, N_INST / TBM, NMC);
        f16_gemm<false><<<g, 256, SMEM_T1>>>(
            Xh, O1T, nullptr, nullptr, zh,
            nullptr, nullptr, nullptr, nullptr,
            N_INST, RF, D0,
            0LL, (long long)RF * D0, (long long)N_INST * RF, 0LL);
    }
    // 4. phi1 = LN(rf(z1))
    rfln_kernel<<<(NMC * N_INST) / 8, 256>>>(zh, phih);

    // 5-8. prep: W1 cvt, Omega2 transpose, zero, W2/Wm transposes
    {
        long long nW1 = (long long)(2 * RF) * D1;
        cvt_kernel<<<(unsigned)((nW1 + 255) / 256), 256>>>(W1, W1h, nW1);
    }
    splitT_kernel<<<dim3(D1 / 32, RF / 32, NMC), dim3(32, 8)>>>(Omega2, O2T, D1, RF);
    zero_kernel<<<128, 256>>>(out, seg);
    splitT_kernel<<<dim3((2 * RF) / 32, D2 / 32, 1), dim3(32, 8)>>>(W2, W2T, 2 * RF, D2);
    splitT_kernel<<<dim3(D2 / 32, (NATT * DATT) / 32, 1), dim3(32, 8)>>>(Wm, WmT, D2, NATT * DATT);

    // 9. bias2[m] = b1 @ Omega2[m]
    bias2_kernel<<<dim3(RF / 8, NMC), 256>>>(b1, O2T, bias2);

    // 10. Fusion precompute: W12T[m] = (W1 @ Omega2[m])^T
    //     = f16_gemm(A = O2T[m] [512 x 512], B = W1h as [N=1024][K=512])
    {
        dim3 g((2 * RF) / TBN, RF / TBM, NMC);
        f16_gemm<false><<<g, 256, SMEM_T1>>>(
            O2T, W1h, nullptr, nullptr, W12T,
            nullptr, nullptr, nullptr, nullptr,
            RF, 2 * RF, D1,
            (long long)RF * D1, 0LL, (long long)RF * 2 * RF, 0LL);
    }

    // 11. z2[m] = phi1[m] @ W12T[m]^T + bias2[m]  -> fp16 zh  (h1/GEMM3 eliminated)
    {
        dim3 g(RF / TBN, N_INST / TBM, NMC);
        f16_gemm<false><<<g, 256, SMEM_T1>>>(
            phih, W12T, bias2, nullptr, zh,
            nullptr, nullptr, nullptr, nullptr,
            N_INST, RF, 2 * RF,
            (long long)N_INST * 2 * RF, (long long)RF * 2 * RF,
            (long long)N_INST * RF, (long long)RF);
    }
    // 12. phi2 = LN(rf(z2))
    rfln_kernel<<<(NMC * N_INST) / 8, 256>>>(zh, phih);

    // 13. emb = phi2 @ W2 + b2 -> fp16
    {
        dim3 g(D2 / TBN, (NMC * N_INST) / TBM, 1);
        f16_gemm<false><<<g, 256, SMEM_T1>>>(
            phih, W2T, b2, nullptr, embh,
            nullptr, nullptr, nullptr, nullptr,
            NMC * N_INST, D2, 2 * RF, 0LL, 0LL, 0LL, 0LL);
    }
    // 14. attention scores + segment exp-sums
    scores_kernel<<<(NMC * N_INST * 32 + 255) / 256, 256>>>(embh, Ws, bs, X_idx, expP, seg);

    // 15. emb_new GEMM with fused relu + softmax-weight + segment pooling
    {
        dim3 g((NATT * DATT) / TBN, (NMC * N_INST) / TBM, 1);
        f16_gemm<true><<<g, 256, SMEM_T1>>>(
            embh, WmT, bm, nullptr, nullptr,
            expP, seg, X_idx, out,
            NMC * N_INST, NATT * DATT, D2, 0LL, 0LL, 0LL, 0LL);
    }
}

// round 16
// speedup vs baseline: 1.4883x; 1.0150x over previous
#include <cuda_runtime.h>
#include <cuda_fp16.h>
#include <math.h>
#include <stdint.h>

// Problem constants
#define N_INST 16384
#define BAGS   64
#define NMC    4
#define RF     512
#define D0     1024
#define D1     512
#define D2     256
#define NATT   4
#define DATT   32

// ---------------------------------------------------------------------------
// Scratch (static device globals: allocation-guard safe)
// ---------------------------------------------------------------------------
__device__ float g_expP [(size_t)N_INST * NMC * NATT];
__device__ float g_seg  [BAGS * NMC * NATT];
__device__ float g_bias2[NMC * RF];
__device__ float g_W2s  [(size_t)(2 * RF) * NATT];   // W2@Ws  [1024][4] fp32
__device__ float g_biass[NATT];                      // b2@Ws + bs
__device__ float g_biasm[NATT * DATT];               // b2@Wm + bm

__device__ __half g_Xh   [(size_t)N_INST * D0];
__device__ __half g_zh   [(size_t)NMC * N_INST * RF];
__device__ __half g_phih [(size_t)NMC * N_INST * 2 * RF];
// fp16 weights
__device__ __half g_O1T  [(size_t)NMC * RF * D0];
__device__ __half g_O2T  [(size_t)NMC * RF * D1];
__device__ __half g_W1h  [(size_t)(2 * RF) * D1];
__device__ __half g_W12T [(size_t)NMC * RF * 2 * RF];
__device__ __half g_W2h  [(size_t)(2 * RF) * D2];    // W2 cast [1024][256]
__device__ __half g_WmT  [(size_t)(NATT * DATT) * D2];
__device__ __half g_W2WmT[(size_t)(NATT * DATT) * 2 * RF]; // (W2@Wm)^T [128][1024]

// ---------------------------------------------------------------------------
#define CP_ASYNC16(smem_u32, gptr) \
    asm volatile("cp.async.cg.shared.global [%0], [%1], 16;\n" \
                 :: "r"(smem_u32), "l"(gptr))
#define CP_COMMIT()  asm volatile("cp.async.commit_group;\n")
#define CP_WAIT(n)   asm volatile("cp.async.wait_group %0;\n" :: "n"(n))

#define MMA_F16(c, a0, a1, a2, a3, b0, b1) \
    asm volatile("mma.sync.aligned.m16n8k16.row.col.f32.f16.f16.f32 " \
                 "{%0,%1,%2,%3}, {%4,%5,%6,%7}, {%8,%9}, {%0,%1,%2,%3};" \
                 : "+f"((c)[0]), "+f"((c)[1]), "+f"((c)[2]), "+f"((c)[3]) \
                 : "r"(a0), "r"(a1), "r"(a2), "r"(a3), "r"(b0), "r"(b1))

#define LDSM4(r0, r1, r2, r3, addr) \
    asm volatile("ldmatrix.sync.aligned.m8n8.x4.shared.b16 {%0,%1,%2,%3}, [%4];" \
                 : "=r"(r0), "=r"(r1), "=r"(r2), "=r"(r3) : "r"(addr))

// ---------------------------------------------------------------------------
// fp16 tensor-core GEMM. C[M,N] = A[M,K] @ B^T (+bias); B TRANSPOSED [N][K].
// Block tile 128x128x32, 256 threads, warp tile 32x64, 2 CTA/SM,
// 4-buffer cp.async pipeline, single __syncthreads per stage.
// POOL=true: fused relu + softmax-weight + segment-sum epilogue.
// ---------------------------------------------------------------------------
#define TBM 128
#define TBN 128
#define TBK 32
#define LDK 40
#define TILE_ELEMS (128 * LDK)
#define NBUF 4
#define SMEM_T1 (NBUF * 2 * TILE_ELEMS * 2)   // 81920

template<bool POOL>
__global__ __launch_bounds__(256, 2) void f16_gemm(
    const __half* __restrict__ Ah, const __half* __restrict__ BhT,
    const float* __restrict__ bias,
    float* __restrict__ C, __half* __restrict__ Chi,
    const float* __restrict__ expP, const float* __restrict__ segp,
    const int* __restrict__ idx, float* __restrict__ outp,
    int M, int Ncols, int K,
    long long sA, long long sB, long long sC, long long sBias)
{
    constexpr int STAGE_ELEMS = 2 * TILE_ELEMS;

    Ah  += (long long)blockIdx.z * sA;
    BhT += (long long)blockIdx.z * sB;
    if (C)    C    += (long long)blockIdx.z * sC;
    if (Chi)  Chi  += (long long)blockIdx.z * sC;
    if (bias) bias += (long long)blockIdx.z * sBias;

    extern __shared__ __half smem[];

    const int tid  = threadIdx.x;
    const int wid  = tid >> 5;
    const int lane = tid & 31;
    const int wm   = (wid >> 1) * 32;
    const int wn   = (wid & 1) * 64;
    const int brow = blockIdx.y * TBM;
    const int bcol = blockIdx.x * TBN;
    const int lg   = lane >> 2;
    const int lq2  = (lane & 3) * 2;

    float acc[2][8][4];
#pragma unroll
    for (int mi = 0; mi < 2; mi++)
#pragma unroll
        for (int ni = 0; ni < 8; ni++)
#pragma unroll
            for (int j = 0; j < 4; j++) acc[mi][ni][j] = 0.f;

    const int nStages = K / TBK;
    const uint32_t smemBase = (uint32_t)__cvta_generic_to_shared(smem);

    const int stR = tid >> 1;
    const int stC = (tid & 1) * 16;

    auto stage_cpasync = [&](int buf, int k0) {
        const uint32_t sbb = smemBase + buf * (STAGE_ELEMS * 2);
#pragma unroll
        for (int i = 0; i < 2; i++) {
            const int c = stC + i * 8;
            CP_ASYNC16(sbb + (stR * LDK + c) * 2,
                       Ah + (long long)(brow + stR) * K + k0 + c);
            CP_ASYNC16(sbb + (TILE_ELEMS + stR * LDK + c) * 2,
                       BhT + (long long)(bcol + stR) * K + k0 + c);
        }
        CP_COMMIT();
    };

    const uint32_t aOff =
        (uint32_t)(((lane & 15) * LDK + (lane >> 4) * 8) * 2);
    const uint32_t bOff =
        (uint32_t)((((lane & 7) + ((lane >> 4) << 3)) * LDK +
                    (((lane >> 3) & 1) << 3)) * 2);

    stage_cpasync(0, 0);
    if (nStages > 1) stage_cpasync(1, TBK);

    for (int s = 0; s < nStages; s++) {
        const int buf = s & 3;
        if (s + 2 < nStages) {
            stage_cpasync((s + 2) & 3, (s + 2) * TBK);
            CP_WAIT(2);
        } else if (s + 1 < nStages) {
            CP_WAIT(1);
        } else {
            CP_WAIT(0);
        }
        __syncthreads();   // single barrier per stage (NBUF=4 hazard-free)

        const uint32_t tb  = smemBase + buf * (STAGE_ELEMS * 2);
        const uint32_t AhB = tb;
        const uint32_t BhB = tb + TILE_ELEMS * 2;

#pragma unroll
        for (int kk = 0; kk < 2; kk++) {
            const uint32_t kByte = kk * 16 * 2;
            uint32_t ah[2][4];
#pragma unroll
            for (int mi = 0; mi < 2; mi++) {
                const uint32_t rowB = (uint32_t)((wm + mi * 16) * LDK * 2);
                LDSM4(ah[mi][0], ah[mi][1], ah[mi][2], ah[mi][3],
                      AhB + rowB + aOff + kByte);
            }
#pragma unroll
            for (int p = 0; p < 4; p++) {
                const uint32_t nB = (uint32_t)((wn + p * 16) * LDK * 2);
                uint32_t bh0, bh1, bh2, bh3;
                LDSM4(bh0, bh1, bh2, bh3, BhB + nB + bOff + kByte);
#pragma unroll
                for (int mi = 0; mi < 2; mi++) {
                    MMA_F16(acc[mi][p * 2],     ah[mi][0], ah[mi][1], ah[mi][2], ah[mi][3], bh0, bh1);
                    MMA_F16(acc[mi][p * 2 + 1], ah[mi][0], ah[mi][1], ah[mi][2], ah[mi][3], bh2, bh3);
                }
            }
        }
    }

    if (!POOL) {
#pragma unroll
        for (int mi = 0; mi < 2; mi++) {
            const int row0 = brow + wm + mi * 16 + lg;
#pragma unroll
            for (int ni = 0; ni < 8; ni++) {
                const int col = bcol + wn + ni * 8 + lq2;
                float b0 = 0.f, b1 = 0.f;
                if (bias) { b0 = bias[col]; b1 = bias[col + 1]; }
                float v0 = acc[mi][ni][0] + b0;
                float v1 = acc[mi][ni][1] + b1;
                float v2 = acc[mi][ni][2] + b0;
                float v3 = acc[mi][ni][3] + b1;
                if (C) {
                    *(float2*)(C + (long long)row0 * Ncols + col)       = make_float2(v0, v1);
                    *(float2*)(C + (long long)(row0 + 8) * Ncols + col) = make_float2(v2, v3);
                }
                if (Chi) {
                    *(__half2*)(Chi + (long long)row0 * Ncols + col) =
                        __halves2half2(__float2half_rn(v0), __float2half_rn(v1));
                    *(__half2*)(Chi + (long long)(row0 + 8) * Ncols + col) =
                        __halves2half2(__float2half_rn(v2), __float2half_rn(v3));
                }
            }
        }
    } else {
        // Fused pooling epilogue:
        // out[b, m, col] += relu(v + bias) * expP[n,m,k]/seg[b,m,k]
        const int rbase = brow + wm + lg;
        int bags[4], ns[4];
        const int mMC = rbase >> 14;            // rbase / N_INST
#pragma unroll
        for (int rr = 0; rr < 4; rr++) {
            const int g = rbase + rr * 8;
            ns[rr]   = g & (N_INST - 1);
            bags[rr] = idx[ns[rr]];
        }
#pragma unroll
        for (int ni = 0; ni < 8; ni++) {
            const int col = bcol + wn + ni * 8 + lq2;
            const int k   = col >> 5;
            const float b0 = bias[col];
            const float b1 = bias[col + 1];
            float v[4][2] = {
                {acc[0][ni][0], acc[0][ni][1]},
                {acc[0][ni][2], acc[0][ni][3]},
                {acc[1][ni][0], acc[1][ni][1]},
                {acc[1][ni][2], acc[1][ni][3]},
            };
            float s0 = 0.f, s1 = 0.f;
            int curb = bags[0];
#pragma unroll
            for (int rr = 0; rr < 4; rr++) {
                const float p =
                    expP[(((long long)ns[rr] * NMC) + mMC) * NATT + k] /
                    segp[(((long long)bags[rr] * NMC) + mMC) * NATT + k];
                const float w0 = fmaxf(v[rr][0] + b0, 0.f) * p;
                const float w1 = fmaxf(v[rr][1] + b1, 0.f) * p;
                if (bags[rr] != curb) {
                    float* o = outp + (((long long)curb * NMC) + mMC) * (NATT * DATT) + col;
                    atomicAdd(o,     s0);
                    atomicAdd(o + 1, s1);
                    curb = bags[rr];
                    s0 = 0.f; s1 = 0.f;
                }
                s0 += w0; s1 += w1;
            }
            float* o = outp + (((long long)curb * NMC) + mMC) * (NATT * DATT) + col;
            atomicAdd(o,     s0);
            atomicAdd(o + 1, s1);
        }
    }
}

// ---------------------------------------------------------------------------
__global__ __launch_bounds__(256) void cvt_kernel(
    const float* __restrict__ src, __half* __restrict__ dst, long long n)
{
    long long i = (long long)blockIdx.x * blockDim.x + threadIdx.x;
    if (i < n) dst[i] = __float2half_rn(src[i]);
}

// fp32 [K][N] -> transposed fp16 [N][K], 32x32 smem-tiled.
__global__ __launch_bounds__(256) void splitT_kernel(
    const float* __restrict__ src, __half* __restrict__ hT, int K, int N)
{
    __shared__ float t[32][33];
    const long long boff = (long long)blockIdx.z * K * N;
    const int k0 = blockIdx.x * 32;
    const int n0 = blockIdx.y * 32;
    const int tx = threadIdx.x, ty = threadIdx.y;

#pragma unroll
    for (int i = 0; i < 32; i += 8)
        t[ty + i][tx] = src[boff + (long long)(k0 + ty + i) * N + n0 + tx];
    __syncthreads();
#pragma unroll
    for (int i = 0; i < 32; i += 8)
        hT[boff + (long long)(n0 + ty + i) * K + k0 + tx] =
            __float2half_rn(t[tx][ty + i]);
}

// ---------------------------------------------------------------------------
// bias2[m][r] = sum_d b1[d] * O2T[m][r][d]
// ---------------------------------------------------------------------------
__global__ __launch_bounds__(256) void bias2_kernel(
    const float* __restrict__ b1, const __half* __restrict__ O2T,
    float* __restrict__ bias2)
{
    const int warp = threadIdx.x >> 5;
    const int lane = threadIdx.x & 31;
    const int r = blockIdx.x * 8 + warp;
    const int m = blockIdx.y;
    const __half* row = O2T + ((long long)m * RF + r) * D1;
    float s = 0.f;
    for (int d = lane; d < D1; d += 32)
        s = fmaf(__half2float(row[d]), b1[d], s);
#pragma unroll
    for (int o = 16; o > 0; o >>= 1)
        s += __shfl_xor_sync(0xffffffffu, s, o);
    if (lane == 0) bias2[m * RF + r] = s;
}

// ---------------------------------------------------------------------------
// W2s[f][k] = sum_d W2[f][d] * Ws[d][k]; also biass[k] = b2@Ws[:,k] + bs[k].
// One warp per f (1024 rows), grid 128 blocks x 8 warps.
// ---------------------------------------------------------------------------
__global__ __launch_bounds__(256) void w2s_kernel(
    const float* __restrict__ W2, const float* __restrict__ Ws,
    const float* __restrict__ b2, const float* __restrict__ bs,
    float* __restrict__ W2s, float* __restrict__ biass)
{
    const int warp = threadIdx.x >> 5;
    const int lane = threadIdx.x & 31;
    const int f = blockIdx.x * 8 + warp;
    float a0 = 0.f, a1 = 0.f, a2 = 0.f, a3 = 0.f;
    const float* row = W2 + (long long)f * D2;
    for (int d = lane; d < D2; d += 32) {
        float  w  = row[d];
        float4 wv = *(const float4*)(Ws + d * 4);
        a0 = fmaf(w, wv.x, a0);
        a1 = fmaf(w, wv.y, a1);
        a2 = fmaf(w, wv.z, a2);
        a3 = fmaf(w, wv.w, a3);
    }
#pragma unroll
    for (int o = 16; o > 0; o >>= 1) {
        a0 += __shfl_xor_sync(0xffffffffu, a0, o);
        a1 += __shfl_xor_sync(0xffffffffu, a1, o);
        a2 += __shfl_xor_sync(0xffffffffu, a2, o);
        a3 += __shfl_xor_sync(0xffffffffu, a3, o);
    }
    if (lane == 0) {
        float* w = W2s + f * 4;
        w[0] = a0; w[1] = a1; w[2] = a2; w[3] = a3;
    }
    if (blockIdx.x == 0 && threadIdx.x < 4) {
        float s = bs[threadIdx.x];
        for (int d = 0; d < D2; d++)
            s = fmaf(b2[d], Ws[d * 4 + threadIdx.x], s);
        biass[threadIdx.x] = s;
    }
}

// ---------------------------------------------------------------------------
// biasm[e] = sum_d b2[d] * Wm[d][e] + bm[e]   (e = 0..127, warp per e)
// ---------------------------------------------------------------------------
__global__ __launch_bounds__(256) void biasm_kernel(
    const float* __restrict__ b2, const float* __restrict__ Wm,
    const float* __restrict__ bm, float* __restrict__ biasm)
{
    const int warp = threadIdx.x >> 5;
    const int lane = threadIdx.x & 31;
    const int e = blockIdx.x * 8 + warp;
    float s = 0.f;
    for (int d = lane; d < D2; d += 32)
        s = fmaf(b2[d], Wm[(long long)d * (NATT * DATT) + e], s);
#pragma unroll
    for (int o = 16; o > 0; o >>= 1)
        s += __shfl_xor_sync(0xffffffffu, s, o);
    if (lane == 0) biasm[e] = s + bm[e];
}

// ---------------------------------------------------------------------------
// Fused RBF random features + LayerNorm, warp-per-row, fp16 z input.
// ---------------------------------------------------------------------------
__global__ __launch_bounds__(256) void rfln_kernel(
    const __half* __restrict__ z, __half* __restrict__ phih)
{
    const int warp = threadIdx.x >> 5;
    const int lane = threadIdx.x & 31;
    const long long row = (long long)blockIdx.x * 8 + warp;

    const __half2* z2 = (const __half2*)(z + row * RF);
    __half2* ph2 = (__half2*)(phih + row * (2 * RF));
    const float scale = 0.044194173824159216f;  // 1/sqrt(512)

    float c[16], s[16];
    float sum = 0.f, sq = 0.f;
#pragma unroll
    for (int j = 0; j < 8; j++) {
        __half2 v = z2[j * 32 + lane];
        float vx = __low2float(v), vy = __high2float(v);
        float c0 = __cosf(vx) * scale;
        float c1 = __cosf(vy) * scale;
        float s0 = __sinf(vx) * scale;
        float s1 = __sinf(vy) * scale;
        c[2 * j] = c0; c[2 * j + 1] = c1;
        s[2 * j] = s0; s[2 * j + 1] = s1;
        sum += c0 + c1 + s0 + s1;
        sq  += c0 * c0 + c1 * c1 + s0 * s0 + s1 * s1;
    }
#pragma unroll
    for (int o = 16; o > 0; o >>= 1) {
        sum += __shfl_xor_sync(0xffffffffu, sum, o);
        sq  += __shfl_xor_sync(0xffffffffu, sq,  o);
    }
    const float mean = sum * (1.f / 1024.f);
    const float var  = sq * (1.f / 1024.f) - mean * mean;
    const float inv  = rsqrtf(var + 1e-5f);

#pragma unroll
    for (int j = 0; j < 8; j++) {
        ph2[j * 32 + lane] =
            __halves2half2(__float2half_rn((c[2 * j]     - mean) * inv),
                           __float2half_rn((c[2 * j + 1] - mean) * inv));
        ph2[256 + j * 32 + lane] =
            __halves2half2(__float2half_rn((s[2 * j]     - mean) * inv),
                           __float2half_rn((s[2 * j + 1] - mean) * inv));
    }
}

// ---------------------------------------------------------------------------
// Attention scores DIRECT from phi2: score[k] = phi2 . W2s[:,k] + biass[k].
// One warp per (m,n); K = 1024.
// ---------------------------------------------------------------------------
__global__ __launch_bounds__(256) void scores_kernel(
    const __half* __restrict__ phih, const float* __restrict__ W2s,
    const float* __restrict__ biass, const int* __restrict__ idx,
    float* __restrict__ expP, float* __restrict__ seg)
{
    const int gw   = (blockIdx.x * blockDim.x + threadIdx.x) >> 5;
    const int lane = threadIdx.x & 31;
    if (gw >= NMC * N_INST) return;
    const int m = gw / N_INST;
    const int n = gw - m * N_INST;
    const __half2* e = (const __half2*)(phih + (long long)gw * (2 * RF));

    float a0 = 0.f, a1 = 0.f, a2 = 0.f, a3 = 0.f;
    for (int d = lane; d < RF; d += 32) {   // 512 half2 = 1024 elements
        __half2 ev = e[d];
        float e0 = __low2float(ev), e1 = __high2float(ev);
        float4 w0 = *(const float4*)(W2s + (2 * d) * 4);
        float4 w1 = *(const float4*)(W2s + (2 * d + 1) * 4);
        a0 = fmaf(e0, w0.x, fmaf(e1, w1.x, a0));
        a1 = fmaf(e0, w0.y, fmaf(e1, w1.y, a1));
        a2 = fmaf(e0, w0.z, fmaf(e1, w1.z, a2));
        a3 = fmaf(e0, w0.w, fmaf(e1, w1.w, a3));
    }
#pragma unroll
    for (int o = 16; o > 0; o >>= 1) {
        a0 += __shfl_down_sync(0xffffffffu, a0, o);
        a1 += __shfl_down_sync(0xffffffffu, a1, o);
        a2 += __shfl_down_sync(0xffffffffu, a2, o);
        a3 += __shfl_down_sync(0xffffffffu, a3, o);
    }
    if (lane == 0) {
        const int b = idx[n];
        const float inv16 = 0.0625f;
        float v0 = expf((a0 + biass[0]) * inv16);
        float v1 = expf((a1 + biass[1]) * inv16);
        float v2 = expf((a2 + biass[2]) * inv16);
        float v3 = expf((a3 + biass[3]) * inv16);
        float* ep = expP + ((long long)n * NMC + m) * NATT;
        ep[0] = v0; ep[1] = v1; ep[2] = v2; ep[3] = v3;
        float* sp = seg + ((long long)b * NMC + m) * NATT;
        atomicAdd(sp + 0, v0);
        atomicAdd(sp + 1, v1);
        atomicAdd(sp + 2, v2);
        atomicAdd(sp + 3, v3);
    }
}

// ---------------------------------------------------------------------------
__global__ void zero_kernel(float* __restrict__ out, float* __restrict__ seg)
{
    const int i = blockIdx.x * blockDim.x + threadIdx.x;
    if (i < BAGS * NMC * NATT * DATT) out[i] = 0.f;
    if (i < BAGS * NMC * NATT)        seg[i] = 0.f;
}

// ---------------------------------------------------------------------------
extern "C" void kernel_launch(void* const* d_in, const int* in_sizes, int n_in,
                              void* d_out, int out_size)
{
    const float* X      = (const float*)d_in[0];
    const int*   X_idx  = (const int*)  d_in[1];
    const float* Omega1 = (const float*)d_in[2];
    const float* Omega2 = (const float*)d_in[3];
    const float* W1     = (const float*)d_in[4];
    const float* b1     = (const float*)d_in[5];
    const float* W2     = (const float*)d_in[6];
    const float* b2     = (const float*)d_in[7];
    const float* Ws     = (const float*)d_in[8];
    const float* bs     = (const float*)d_in[9];
    const float* Wm     = (const float*)d_in[10];
    const float* bm     = (const float*)d_in[11];
    float* out = (float*)d_out;

    static bool cfg = false;
    if (!cfg) {
        cudaFuncSetAttribute(f16_gemm<false>,
                             cudaFuncAttributeMaxDynamicSharedMemorySize, SMEM_T1);
        cudaFuncSetAttribute(f16_gemm<true>,
                             cudaFuncAttributeMaxDynamicSharedMemorySize, SMEM_T1);
        cfg = true;
    }

    float *expP, *seg, *bias2, *W2s, *biass, *biasm;
    __half *Xh, *zh, *phih;
    __half *O1T, *O2T, *W1h, *W12T, *W2h, *WmT, *W2WmT;
    cudaGetSymbolAddress((void**)&expP,  g_expP);
    cudaGetSymbolAddress((void**)&seg,   g_seg);
    cudaGetSymbolAddress((void**)&bias2, g_bias2);
    cudaGetSymbolAddress((void**)&W2s,   g_W2s);
    cudaGetSymbolAddress((void**)&biass, g_biass);
    cudaGetSymbolAddress((void**)&biasm, g_biasm);
    cudaGetSymbolAddress((void**)&Xh,    g_Xh);
    cudaGetSymbolAddress((void**)&zh,    g_zh);
    cudaGetSymbolAddress((void**)&phih,  g_phih);
    cudaGetSymbolAddress((void**)&O1T,   g_O1T);
    cudaGetSymbolAddress((void**)&O2T,   g_O2T);
    cudaGetSymbolAddress((void**)&W1h,   g_W1h);
    cudaGetSymbolAddress((void**)&W12T,  g_W12T);
    cudaGetSymbolAddress((void**)&W2h,   g_W2h);
    cudaGetSymbolAddress((void**)&WmT,   g_WmT);
    cudaGetSymbolAddress((void**)&W2WmT, g_W2WmT);

    // 1. Omega1 transpose
    splitT_kernel<<<dim3(D0 / 32, RF / 32, NMC), dim3(32, 8)>>>(Omega1, O1T, D0, RF);
    // 2. X -> fp16
    {
        long long nX = (long long)N_INST * D0;
        cvt_kernel<<<(unsigned)((nX + 255) / 256), 256>>>(X, Xh, nX);
    }
    // 3. GEMM1: z1[m] = X @ Omega1[m] -> fp16 zh
    {
        dim3 g(RF / TBN, N_INST / TBM, NMC);
        f16_gemm<false><<<g, 256, SMEM_T1>>>(
            Xh, O1T, nullptr, nullptr, zh,
            nullptr, nullptr, nullptr, nullptr,
            N_INST, RF, D0,
            0LL, (long long)RF * D0, (long long)N_INST * RF, 0LL);
    }
    // 4. phi1 = LN(rf(z1))
    rfln_kernel<<<(NMC * N_INST) / 8, 256>>>(zh, phih);

    // 5-9. prep: W1 cvt, Omega2 transpose, zero, W2 cvt, Wm transpose
    {
        long long nW1 = (long long)(2 * RF) * D1;
        cvt_kernel<<<(unsigned)((nW1 + 255) / 256), 256>>>(W1, W1h, nW1);
    }
    splitT_kernel<<<dim3(D1 / 32, RF / 32, NMC), dim3(32, 8)>>>(Omega2, O2T, D1, RF);
    zero_kernel<<<128, 256>>>(out, seg);
    {
        long long nW2 = (long long)(2 * RF) * D2;
        cvt_kernel<<<(unsigned)((nW2 + 255) / 256), 256>>>(W2, W2h, nW2);
    }
    splitT_kernel<<<dim3(D2 / 32, (NATT * DATT) / 32, 1), dim3(32, 8)>>>(Wm, WmT, D2, NATT * DATT);

    // 10-12. small fused-weight precomputes
    bias2_kernel<<<dim3(RF / 8, NMC), 256>>>(b1, O2T, bias2);
    w2s_kernel<<<(2 * RF) / 8, 256>>>(W2, Ws, b2, bs, W2s, biass);
    biasm_kernel<<<(NATT * DATT) / 8, 256>>>(b2, Wm, bm, biasm);

    // 13. W12T[m] = (W1 @ Omega2[m])^T
    {
        dim3 g((2 * RF) / TBN, RF / TBM, NMC);
        f16_gemm<false><<<g, 256, SMEM_T1>>>(
            O2T, W1h, nullptr, nullptr, W12T,
            nullptr, nullptr, nullptr, nullptr,
            RF, 2 * RF, D1,
            (long long)RF * D1, 0LL, (long long)RF * 2 * RF, 0LL);
    }
    // 14. W2WmT = (W2 @ Wm)^T : A = WmT [128 x 256], B = W2h [N=1024][K=256]
    {
        dim3 g((2 * RF) / TBN, (NATT * DATT) / TBM, 1);
        f16_gemm<false><<<g, 256, SMEM_T1>>>(
            WmT, W2h, nullptr, nullptr, W2WmT,
            nullptr, nullptr, nullptr, nullptr,
            NATT * DATT, 2 * RF, D2, 0LL, 0LL, 0LL, 0LL);
    }

    // 15. z2[m] = phi1[m] @ W12T[m]^T + bias2[m] -> fp16 zh
    {
        dim3 g(RF / TBN, N_INST / TBM, NMC);
        f16_gemm<false><<<g, 256, SMEM_T1>>>(
            phih, W12T, bias2, nullptr, zh,
            nullptr, nullptr, nullptr, nullptr,
            N_INST, RF, 2 * RF,
            (long long)N_INST * 2 * RF, (long long)RF * 2 * RF,
            (long long)N_INST * RF, (long long)RF);
    }
    // 16. phi2 = LN(rf(z2))
    rfln_kernel<<<(NMC * N_INST) / 8, 256>>>(zh, phih);

    // 17. scores directly from phi2 (emb GEMM eliminated)
    scores_kernel<<<(NMC * N_INST * 32 + 255) / 256, 256>>>(
        phih, W2s, biass, X_idx, expP, seg);

    // 18. fused emb_new: phi2 @ W2WmT^T + biasm, with relu+softmax+pool epilogue
    {
        dim3 g((NATT * DATT) / TBN, (NMC * N_INST) / TBM, 1);
        f16_gemm<true><<<g, 256, SMEM_T1>>>(
            phih, W2WmT, biasm, nullptr, nullptr,
            expP, seg, X_idx, out,
            NMC * N_INST, NATT * DATT, 2 * RF, 0LL, 0LL, 0LL, 0LL);
    }
}

// round 17
// speedup vs baseline: 1.5423x; 1.0363x over previous
#include <cuda_runtime.h>
#include <cuda_fp16.h>
#include <math.h>
#include <stdint.h>

// Problem constants
#define N_INST 16384
#define BAGS   64
#define NMC    4
#define RF     512
#define D0     1024
#define D1     512
#define D2     256
#define NATT   4
#define DATT   32

// ---------------------------------------------------------------------------
// Scratch (static device globals: allocation-guard safe)
// ---------------------------------------------------------------------------
__device__ float g_expP [(size_t)N_INST * NMC * NATT];
__device__ float g_seg  [BAGS * NMC * NATT];
__device__ float g_bias2[NMC * RF];
__device__ float g_W2s  [(size_t)(2 * RF) * NATT];   // W2@Ws  [1024][4] fp32
__device__ float g_biass[NATT];                      // b2@Ws + bs
__device__ float g_biasm[NATT * DATT];               // b2@Wm + bm

__device__ __half g_Xh   [(size_t)N_INST * D0];
__device__ __half g_zh   [(size_t)NMC * N_INST * RF];
__device__ __half g_phih [(size_t)NMC * N_INST * 2 * RF];
// fp16 weights
__device__ __half g_O1T  [(size_t)NMC * RF * D0];
__device__ __half g_O2T  [(size_t)NMC * RF * D1];
__device__ __half g_W1h  [(size_t)(2 * RF) * D1];
__device__ __half g_W12T [(size_t)NMC * RF * 2 * RF];
__device__ __half g_W2h  [(size_t)(2 * RF) * D2];
__device__ __half g_WmT  [(size_t)(NATT * DATT) * D2];
__device__ __half g_W2WmT[(size_t)(NATT * DATT) * 2 * RF];

// ---------------------------------------------------------------------------
#define CP_ASYNC16(smem_u32, gptr) \
    asm volatile("cp.async.cg.shared.global [%0], [%1], 16;\n" \
                 :: "r"(smem_u32), "l"(gptr))
#define CP_COMMIT()  asm volatile("cp.async.commit_group;\n")
#define CP_WAIT(n)   asm volatile("cp.async.wait_group %0;\n" :: "n"(n))

#define MMA_F16(c, a0, a1, a2, a3, b0, b1) \
    asm volatile("mma.sync.aligned.m16n8k16.row.col.f32.f16.f16.f32 " \
                 "{%0,%1,%2,%3}, {%4,%5,%6,%7}, {%8,%9}, {%0,%1,%2,%3};" \
                 : "+f"((c)[0]), "+f"((c)[1]), "+f"((c)[2]), "+f"((c)[3]) \
                 : "r"(a0), "r"(a1), "r"(a2), "r"(a3), "r"(b0), "r"(b1))

#define LDSM4(r0, r1, r2, r3, addr) \
    asm volatile("ldmatrix.sync.aligned.m8n8.x4.shared.b16 {%0,%1,%2,%3}, [%4];" \
                 : "=r"(r0), "=r"(r1), "=r"(r2), "=r"(r3) : "r"(addr))

// ---------------------------------------------------------------------------
// fp16 tensor-core GEMM. C[M,N] = A[M,K] @ B^T (+bias); B TRANSPOSED [N][K].
// Block tile 128x128x32, 256 threads, warp tile 32x64, 2 CTA/SM,
// 4-buffer cp.async pipeline, single __syncthreads per stage.
// POOL=true: fused relu + softmax-weight + segment-sum epilogue.
// ---------------------------------------------------------------------------
#define TBM 128
#define TBN 128
#define TBK 32
#define LDK 40
#define TILE_ELEMS (128 * LDK)
#define NBUF 4
#define SMEM_T1 (NBUF * 2 * TILE_ELEMS * 2)   // 81920

template<bool POOL>
__global__ __launch_bounds__(256, 2) void f16_gemm(
    const __half* __restrict__ Ah, const __half* __restrict__ BhT,
    const float* __restrict__ bias,
    float* __restrict__ C, __half* __restrict__ Chi,
    const float* __restrict__ expP, const float* __restrict__ segp,
    const int* __restrict__ idx, float* __restrict__ outp,
    int M, int Ncols, int K,
    long long sA, long long sB, long long sC, long long sBias)
{
    constexpr int STAGE_ELEMS = 2 * TILE_ELEMS;

    Ah  += (long long)blockIdx.z * sA;
    BhT += (long long)blockIdx.z * sB;
    if (C)    C    += (long long)blockIdx.z * sC;
    if (Chi)  Chi  += (long long)blockIdx.z * sC;
    if (bias) bias += (long long)blockIdx.z * sBias;

    extern __shared__ __half smem[];

    const int tid  = threadIdx.x;
    const int wid  = tid >> 5;
    const int lane = tid & 31;
    const int wm   = (wid >> 1) * 32;
    const int wn   = (wid & 1) * 64;
    const int brow = blockIdx.y * TBM;
    const int bcol = blockIdx.x * TBN;
    const int lg   = lane >> 2;
    const int lq2  = (lane & 3) * 2;

    float acc[2][8][4];
#pragma unroll
    for (int mi = 0; mi < 2; mi++)
#pragma unroll
        for (int ni = 0; ni < 8; ni++)
#pragma unroll
            for (int j = 0; j < 4; j++) acc[mi][ni][j] = 0.f;

    const int nStages = K / TBK;
    const uint32_t smemBase = (uint32_t)__cvta_generic_to_shared(smem);

    const int stR = tid >> 1;
    const int stC = (tid & 1) * 16;

    auto stage_cpasync = [&](int buf, int k0) {
        const uint32_t sbb = smemBase + buf * (STAGE_ELEMS * 2);
#pragma unroll
        for (int i = 0; i < 2; i++) {
            const int c = stC + i * 8;
            CP_ASYNC16(sbb + (stR * LDK + c) * 2,
                       Ah + (long long)(brow + stR) * K + k0 + c);
            CP_ASYNC16(sbb + (TILE_ELEMS + stR * LDK + c) * 2,
                       BhT + (long long)(bcol + stR) * K + k0 + c);
        }
        CP_COMMIT();
    };

    const uint32_t aOff =
        (uint32_t)(((lane & 15) * LDK + (lane >> 4) * 8) * 2);
    const uint32_t bOff =
        (uint32_t)((((lane & 7) + ((lane >> 4) << 3)) * LDK +
                    (((lane >> 3) & 1) << 3)) * 2);

    stage_cpasync(0, 0);
    if (nStages > 1) stage_cpasync(1, TBK);

    for (int s = 0; s < nStages; s++) {
        const int buf = s & 3;
        if (s + 2 < nStages) {
            stage_cpasync((s + 2) & 3, (s + 2) * TBK);
            CP_WAIT(2);
        } else if (s + 1 < nStages) {
            CP_WAIT(1);
        } else {
            CP_WAIT(0);
        }
        __syncthreads();   // single barrier per stage (NBUF=4 hazard-free)

        const uint32_t tb  = smemBase + buf * (STAGE_ELEMS * 2);
        const uint32_t AhB = tb;
        const uint32_t BhB = tb + TILE_ELEMS * 2;

#pragma unroll
        for (int kk = 0; kk < 2; kk++) {
            const uint32_t kByte = kk * 16 * 2;
            uint32_t ah[2][4];
#pragma unroll
            for (int mi = 0; mi < 2; mi++) {
                const uint32_t rowB = (uint32_t)((wm + mi * 16) * LDK * 2);
                LDSM4(ah[mi][0], ah[mi][1], ah[mi][2], ah[mi][3],
                      AhB + rowB + aOff + kByte);
            }
#pragma unroll
            for (int p = 0; p < 4; p++) {
                const uint32_t nB = (uint32_t)((wn + p * 16) * LDK * 2);
                uint32_t bh0, bh1, bh2, bh3;
                LDSM4(bh0, bh1, bh2, bh3, BhB + nB + bOff + kByte);
#pragma unroll
                for (int mi = 0; mi < 2; mi++) {
                    MMA_F16(acc[mi][p * 2],     ah[mi][0], ah[mi][1], ah[mi][2], ah[mi][3], bh0, bh1);
                    MMA_F16(acc[mi][p * 2 + 1], ah[mi][0], ah[mi][1], ah[mi][2], ah[mi][3], bh2, bh3);
                }
            }
        }
    }

    if (!POOL) {
#pragma unroll
        for (int mi = 0; mi < 2; mi++) {
            const int row0 = brow + wm + mi * 16 + lg;
#pragma unroll
            for (int ni = 0; ni < 8; ni++) {
                const int col = bcol + wn + ni * 8 + lq2;
                float b0 = 0.f, b1 = 0.f;
                if (bias) { b0 = bias[col]; b1 = bias[col + 1]; }
                float v0 = acc[mi][ni][0] + b0;
                float v1 = acc[mi][ni][1] + b1;
                float v2 = acc[mi][ni][2] + b0;
                float v3 = acc[mi][ni][3] + b1;
                if (C) {
                    *(float2*)(C + (long long)row0 * Ncols + col)       = make_float2(v0, v1);
                    *(float2*)(C + (long long)(row0 + 8) * Ncols + col) = make_float2(v2, v3);
                }
                if (Chi) {
                    *(__half2*)(Chi + (long long)row0 * Ncols + col) =
                        __halves2half2(__float2half_rn(v0), __float2half_rn(v1));
                    *(__half2*)(Chi + (long long)(row0 + 8) * Ncols + col) =
                        __halves2half2(__float2half_rn(v2), __float2half_rn(v3));
                }
            }
        }
    } else {
        // Fused pooling epilogue:
        // out[b, m, col] += relu(v + bias) * expP[n,m,k]/seg[b,m,k]
        const int rbase = brow + wm + lg;
        int bags[4], ns[4];
        const int mMC = rbase >> 14;            // rbase / N_INST
#pragma unroll
        for (int rr = 0; rr < 4; rr++) {
            const int g = rbase + rr * 8;
            ns[rr]   = g & (N_INST - 1);
            bags[rr] = idx[ns[rr]];
        }
#pragma unroll
        for (int ni = 0; ni < 8; ni++) {
            const int col = bcol + wn + ni * 8 + lq2;
            const int k   = col >> 5;
            const float b0 = bias[col];
            const float b1 = bias[col + 1];
            float v[4][2] = {
                {acc[0][ni][0], acc[0][ni][1]},
                {acc[0][ni][2], acc[0][ni][3]},
                {acc[1][ni][0], acc[1][ni][1]},
                {acc[1][ni][2], acc[1][ni][3]},
            };
            float s0 = 0.f, s1 = 0.f;
            int curb = bags[0];
#pragma unroll
            for (int rr = 0; rr < 4; rr++) {
                const float p =
                    expP[(((long long)ns[rr] * NMC) + mMC) * NATT + k] /
                    segp[(((long long)bags[rr] * NMC) + mMC) * NATT + k];
                const float w0 = fmaxf(v[rr][0] + b0, 0.f) * p;
                const float w1 = fmaxf(v[rr][1] + b1, 0.f) * p;
                if (bags[rr] != curb) {
                    float* o = outp + (((long long)curb * NMC) + mMC) * (NATT * DATT) + col;
                    atomicAdd(o,     s0);
                    atomicAdd(o + 1, s1);
                    curb = bags[rr];
                    s0 = 0.f; s1 = 0.f;
                }
                s0 += w0; s1 += w1;
            }
            float* o = outp + (((long long)curb * NMC) + mMC) * (NATT * DATT) + col;
            atomicAdd(o,     s0);
            atomicAdd(o + 1, s1);
        }
    }
}

// ---------------------------------------------------------------------------
// Merged fp32 -> fp16 convert for X, W1, W2 (segmented by linear index).
// ---------------------------------------------------------------------------
__global__ __launch_bounds__(256) void cvt3_kernel(
    const float* __restrict__ s0, __half* __restrict__ d0, long long n0,
    const float* __restrict__ s1, __half* __restrict__ d1, long long n1,
    const float* __restrict__ s2, __half* __restrict__ d2, long long n2)
{
    long long i = (long long)blockIdx.x * blockDim.x + threadIdx.x;
    if (i < n0) { d0[i] = __float2half_rn(s0[i]); return; }
    i -= n0;
    if (i < n1) { d1[i] = __float2half_rn(s1[i]); return; }
    i -= n1;
    if (i < n2) { d2[i] = __float2half_rn(s2[i]); }
}

// fp32 [K][N] -> transposed fp16 [N][K], 32x32 smem-tiled.
__global__ __launch_bounds__(256) void splitT_kernel(
    const float* __restrict__ src, __half* __restrict__ hT, int K, int N)
{
    __shared__ float t[32][33];
    const long long boff = (long long)blockIdx.z * K * N;
    const int k0 = blockIdx.x * 32;
    const int n0 = blockIdx.y * 32;
    const int tx = threadIdx.x, ty = threadIdx.y;

#pragma unroll
    for (int i = 0; i < 32; i += 8)
        t[ty + i][tx] = src[boff + (long long)(k0 + ty + i) * N + n0 + tx];
    __syncthreads();
#pragma unroll
    for (int i = 0; i < 32; i += 8)
        hT[boff + (long long)(n0 + ty + i) * K + k0 + tx] =
            __float2half_rn(t[tx][ty + i]);
}

// ---------------------------------------------------------------------------
// bias2[m][r] = sum_d b1[d] * O2T[m][r][d]
// ---------------------------------------------------------------------------
__global__ __launch_bounds__(256) void bias2_kernel(
    const float* __restrict__ b1, const __half* __restrict__ O2T,
    float* __restrict__ bias2)
{
    const int warp = threadIdx.x >> 5;
    const int lane = threadIdx.x & 31;
    const int r = blockIdx.x * 8 + warp;
    const int m = blockIdx.y;
    const __half* row = O2T + ((long long)m * RF + r) * D1;
    float s = 0.f;
    for (int d = lane; d < D1; d += 32)
        s = fmaf(__half2float(row[d]), b1[d], s);
#pragma unroll
    for (int o = 16; o > 0; o >>= 1)
        s += __shfl_xor_sync(0xffffffffu, s, o);
    if (lane == 0) bias2[m * RF + r] = s;
}

// ---------------------------------------------------------------------------
// W2s[f][k] = (W2@Ws)[f][k]; biass[k] = b2@Ws[:,k] + bs[k].
// ---------------------------------------------------------------------------
__global__ __launch_bounds__(256) void w2s_kernel(
    const float* __restrict__ W2, const float* __restrict__ Ws,
    const float* __restrict__ b2, const float* __restrict__ bs,
    float* __restrict__ W2s, float* __restrict__ biass)
{
    const int warp = threadIdx.x >> 5;
    const int lane = threadIdx.x & 31;
    const int f = blockIdx.x * 8 + warp;
    float a0 = 0.f, a1 = 0.f, a2 = 0.f, a3 = 0.f;
    const float* row = W2 + (long long)f * D2;
    for (int d = lane; d < D2; d += 32) {
        float  w  = row[d];
        float4 wv = *(const float4*)(Ws + d * 4);
        a0 = fmaf(w, wv.x, a0);
        a1 = fmaf(w, wv.y, a1);
        a2 = fmaf(w, wv.z, a2);
        a3 = fmaf(w, wv.w, a3);
    }
#pragma unroll
    for (int o = 16; o > 0; o >>= 1) {
        a0 += __shfl_xor_sync(0xffffffffu, a0, o);
        a1 += __shfl_xor_sync(0xffffffffu, a1, o);
        a2 += __shfl_xor_sync(0xffffffffu, a2, o);
        a3 += __shfl_xor_sync(0xffffffffu, a3, o);
    }
    if (lane == 0) {
        float* w = W2s + f * 4;
        w[0] = a0; w[1] = a1; w[2] = a2; w[3] = a3;
    }
    if (blockIdx.x == 0 && threadIdx.x < 4) {
        float s = bs[threadIdx.x];
        for (int d = 0; d < D2; d++)
            s = fmaf(b2[d], Ws[d * 4 + threadIdx.x], s);
        biass[threadIdx.x] = s;
    }
}

// ---------------------------------------------------------------------------
// biasm[e] = b2@Wm[:,e] + bm[e]
// ---------------------------------------------------------------------------
__global__ __launch_bounds__(256) void biasm_kernel(
    const float* __restrict__ b2, const float* __restrict__ Wm,
    const float* __restrict__ bm, float* __restrict__ biasm)
{
    const int warp = threadIdx.x >> 5;
    const int lane = threadIdx.x & 31;
    const int e = blockIdx.x * 8 + warp;
    float s = 0.f;
    for (int d = lane; d < D2; d += 32)
        s = fmaf(b2[d], Wm[(long long)d * (NATT * DATT) + e], s);
#pragma unroll
    for (int o = 16; o > 0; o >>= 1)
        s += __shfl_xor_sync(0xffffffffu, s, o);
    if (lane == 0) biasm[e] = s + bm[e];
}

// ---------------------------------------------------------------------------
// Fused RBF features + LayerNorm, warp-per-row, fp16 z input.
// SCORES=true additionally computes the 4 attention scores from the
// in-register phi row (vs W2s), exp-transforms, and does per-bag atomics —
// eliminating the separate scores kernel and its full phi re-read.
// ---------------------------------------------------------------------------
template<bool SCORES>
__global__ __launch_bounds__(256) void rfln_kernel(
    const __half* __restrict__ z, __half* __restrict__ phih,
    const float* __restrict__ W2s, const float* __restrict__ biass,
    const int* __restrict__ idx,
    float* __restrict__ expP, float* __restrict__ seg)
{
    const int warp = threadIdx.x >> 5;
    const int lane = threadIdx.x & 31;
    const long long row = (long long)blockIdx.x * 8 + warp;

    const __half2* z2 = (const __half2*)(z + row * RF);
    __half2* ph2 = (__half2*)(phih + row * (2 * RF));
    const float scale = 0.044194173824159216f;  // 1/sqrt(512)

    float c[16], s[16];
    float sum = 0.f, sq = 0.f;
#pragma unroll
    for (int j = 0; j < 8; j++) {
        __half2 v = z2[j * 32 + lane];
        float vx = __low2float(v), vy = __high2float(v);
        float c0 = __cosf(vx) * scale;
        float c1 = __cosf(vy) * scale;
        float s0 = __sinf(vx) * scale;
        float s1 = __sinf(vy) * scale;
        c[2 * j] = c0; c[2 * j + 1] = c1;
        s[2 * j] = s0; s[2 * j + 1] = s1;
        sum += c0 + c1 + s0 + s1;
        sq  += c0 * c0 + c1 * c1 + s0 * s0 + s1 * s1;
    }
#pragma unroll
    for (int o = 16; o > 0; o >>= 1) {
        sum += __shfl_xor_sync(0xffffffffu, sum, o);
        sq  += __shfl_xor_sync(0xffffffffu, sq,  o);
    }
    const float mean = sum * (1.f / 1024.f);
    const float var  = sq * (1.f / 1024.f) - mean * mean;
    const float inv  = rsqrtf(var + 1e-5f);

    float a0 = 0.f, a1 = 0.f, a2 = 0.f, a3 = 0.f;
#pragma unroll
    for (int j = 0; j < 8; j++) {
        const int fc = 2 * (j * 32 + lane);   // cos features fc, fc+1
        float p0 = (c[2 * j]     - mean) * inv;
        float p1 = (c[2 * j + 1] - mean) * inv;
        float p2 = (s[2 * j]     - mean) * inv;  // sin features 512+fc, +1
        float p3 = (s[2 * j + 1] - mean) * inv;
        ph2[j * 32 + lane]       = __halves2half2(__float2half_rn(p0), __float2half_rn(p1));
        ph2[256 + j * 32 + lane] = __halves2half2(__float2half_rn(p2), __float2half_rn(p3));
        if (SCORES) {
            float4 w0 = *(const float4*)(W2s + (long long)fc * 4);
            float4 w1 = *(const float4*)(W2s + (long long)(fc + 1) * 4);
            float4 w2 = *(const float4*)(W2s + (long long)(512 + fc) * 4);
            float4 w3 = *(const float4*)(W2s + (long long)(513 + fc) * 4);
            a0 = fmaf(p0, w0.x, fmaf(p1, w1.x, fmaf(p2, w2.x, fmaf(p3, w3.x, a0))));
            a1 = fmaf(p0, w0.y, fmaf(p1, w1.y, fmaf(p2, w2.y, fmaf(p3, w3.y, a1))));
            a2 = fmaf(p0, w0.z, fmaf(p1, w1.z, fmaf(p2, w2.z, fmaf(p3, w3.z, a2))));
            a3 = fmaf(p0, w0.w, fmaf(p1, w1.w, fmaf(p2, w2.w, fmaf(p3, w3.w, a3))));
        }
    }
    if (SCORES) {
#pragma unroll
        for (int o = 16; o > 0; o >>= 1) {
            a0 += __shfl_down_sync(0xffffffffu, a0, o);
            a1 += __shfl_down_sync(0xffffffffu, a1, o);
            a2 += __shfl_down_sync(0xffffffffu, a2, o);
            a3 += __shfl_down_sync(0xffffffffu, a3, o);
        }
        if (lane == 0) {
            const int m = (int)(row >> 14);          // row / N_INST
            const int n = (int)(row & (N_INST - 1));
            const int b = idx[n];
            const float inv16 = 0.0625f;             // 1/sqrt(D2)
            float v0 = expf((a0 + biass[0]) * inv16);
            float v1 = expf((a1 + biass[1]) * inv16);
            float v2 = expf((a2 + biass[2]) * inv16);
            float v3 = expf((a3 + biass[3]) * inv16);
            float* ep = expP + ((long long)n * NMC + m) * NATT;
            ep[0] = v0; ep[1] = v1; ep[2] = v2; ep[3] = v3;
            float* sp = seg + ((long long)b * NMC + m) * NATT;
            atomicAdd(sp + 0, v0);
            atomicAdd(sp + 1, v1);
            atomicAdd(sp + 2, v2);
            atomicAdd(sp + 3, v3);
        }
    }
}

// ---------------------------------------------------------------------------
__global__ void zero_kernel(float* __restrict__ out, float* __restrict__ seg)
{
    const int i = blockIdx.x * blockDim.x + threadIdx.x;
    if (i < BAGS * NMC * NATT * DATT) out[i] = 0.f;
    if (i < BAGS * NMC * NATT)        seg[i] = 0.f;
}

// ---------------------------------------------------------------------------
extern "C" void kernel_launch(void* const* d_in, const int* in_sizes, int n_in,
                              void* d_out, int out_size)
{
    const float* X      = (const float*)d_in[0];
    const int*   X_idx  = (const int*)  d_in[1];
    const float* Omega1 = (const float*)d_in[2];
    const float* Omega2 = (const float*)d_in[3];
    const float* W1     = (const float*)d_in[4];
    const float* b1     = (const float*)d_in[5];
    const float* W2     = (const float*)d_in[6];
    const float* b2     = (const float*)d_in[7];
    const float* Ws     = (const float*)d_in[8];
    const float* bs     = (const float*)d_in[9];
    const float* Wm     = (const float*)d_in[10];
    const float* bm     = (const float*)d_in[11];
    float* out = (float*)d_out;

    static bool cfg = false;
    if (!cfg) {
        cudaFuncSetAttribute(f16_gemm<false>,
                             cudaFuncAttributeMaxDynamicSharedMemorySize, SMEM_T1);
        cudaFuncSetAttribute(f16_gemm<true>,
                             cudaFuncAttributeMaxDynamicSharedMemorySize, SMEM_T1);
        cfg = true;
    }

    float *expP, *seg, *bias2, *W2s, *biass, *biasm;
    __half *Xh, *zh, *phih;
    __half *O1T, *O2T, *W1h, *W12T, *W2h, *WmT, *W2WmT;
    cudaGetSymbolAddress((void**)&expP,  g_expP);
    cudaGetSymbolAddress((void**)&seg,   g_seg);
    cudaGetSymbolAddress((void**)&bias2, g_bias2);
    cudaGetSymbolAddress((void**)&W2s,   g_W2s);
    cudaGetSymbolAddress((void**)&biass, g_biass);
    cudaGetSymbolAddress((void**)&biasm, g_biasm);
    cudaGetSymbolAddress((void**)&Xh,    g_Xh);
    cudaGetSymbolAddress((void**)&zh,    g_zh);
    cudaGetSymbolAddress((void**)&phih,  g_phih);
    cudaGetSymbolAddress((void**)&O1T,   g_O1T);
    cudaGetSymbolAddress((void**)&O2T,   g_O2T);
    cudaGetSymbolAddress((void**)&W1h,   g_W1h);
    cudaGetSymbolAddress((void**)&W12T,  g_W12T);
    cudaGetSymbolAddress((void**)&W2h,   g_W2h);
    cudaGetSymbolAddress((void**)&WmT,   g_WmT);
    cudaGetSymbolAddress((void**)&W2WmT, g_W2WmT);

    const long long nX  = (long long)N_INST * D0;
    const long long nW1 = (long long)(2 * RF) * D1;
    const long long nW2 = (long long)(2 * RF) * D2;

    // 1. Omega1 transpose (GEMM1 dependency first)
    splitT_kernel<<<dim3(D0 / 32, RF / 32, NMC), dim3(32, 8)>>>(Omega1, O1T, D0, RF);
    // 2. merged cvt: X, W1, W2 -> fp16
    cvt3_kernel<<<(unsigned)((nX + nW1 + nW2 + 255) / 256), 256>>>(
        X, Xh, nX, W1, W1h, nW1, W2, W2h, nW2);
    // 3. GEMM1: z1[m] = X @ Omega1[m] -> fp16 zh
    {
        dim3 g(RF / TBN, N_INST / TBM, NMC);
        f16_gemm<false><<<g, 256, SMEM_T1>>>(
            Xh, O1T, nullptr, nullptr, zh,
            nullptr, nullptr, nullptr, nullptr,
            N_INST, RF, D0,
            0LL, (long long)RF * D0, (long long)N_INST * RF, 0LL);
    }
    // 4. phi1 = LN(rf(z1))
    rfln_kernel<false><<<(NMC * N_INST) / 8, 256>>>(
        zh, phih, nullptr, nullptr, nullptr, nullptr, nullptr);

    // 5-7. remaining transposes + zero
    splitT_kernel<<<dim3(D1 / 32, RF / 32, NMC), dim3(32, 8)>>>(Omega2, O2T, D1, RF);
    splitT_kernel<<<dim3(D2 / 32, (NATT * DATT) / 32, 1), dim3(32, 8)>>>(Wm, WmT, D2, NATT * DATT);
    zero_kernel<<<128, 256>>>(out, seg);

    // 8-10. fused-weight precomputes
    bias2_kernel<<<dim3(RF / 8, NMC), 256>>>(b1, O2T, bias2);
    w2s_kernel<<<(2 * RF) / 8, 256>>>(W2, Ws, b2, bs, W2s, biass);
    biasm_kernel<<<(NATT * DATT) / 8, 256>>>(b2, Wm, bm, biasm);

    // 11. W12T[m] = (W1 @ Omega2[m])^T
    {
        dim3 g((2 * RF) / TBN, RF / TBM, NMC);
        f16_gemm<false><<<g, 256, SMEM_T1>>>(
            O2T, W1h, nullptr, nullptr, W12T,
            nullptr, nullptr, nullptr, nullptr,
            RF, 2 * RF, D1,
            (long long)RF * D1, 0LL, (long long)RF * 2 * RF, 0LL);
    }
    // 12. W2WmT = (W2 @ Wm)^T
    {
        dim3 g((2 * RF) / TBN, (NATT * DATT) / TBM, 1);
        f16_gemm<false><<<g, 256, SMEM_T1>>>(
            WmT, W2h, nullptr, nullptr, W2WmT,
            nullptr, nullptr, nullptr, nullptr,
            NATT * DATT, 2 * RF, D2, 0LL, 0LL, 0LL, 0LL);
    }

    // 13. z2[m] = phi1[m] @ W12T[m]^T + bias2[m] -> fp16 zh
    {
        dim3 g(RF / TBN, N_INST / TBM, NMC);
        f16_gemm<false><<<g, 256, SMEM_T1>>>(
            phih, W12T, bias2, nullptr, zh,
            nullptr, nullptr, nullptr, nullptr,
            N_INST, RF, 2 * RF,
            (long long)N_INST * 2 * RF, (long long)RF * 2 * RF,
            (long long)N_INST * RF, (long long)RF);
    }
    // 14. phi2 = LN(rf(z2)) + FUSED scores/exp/segment-sums
    rfln_kernel<true><<<(NMC * N_INST) / 8, 256>>>(
        zh, phih, W2s, biass, X_idx, expP, seg);

    // 15. fused emb_new: phi2 @ W2WmT^T + biasm, relu+softmax+pool epilogue
    {
        dim3 g((NATT * DATT) / TBN, (NMC * N_INST) / TBM, 1);
        f16_gemm<true><<<g, 256, SMEM_T1>>>(
            phih, W2WmT, biasm, nullptr, nullptr,
            expP, seg, X_idx, out,
            NMC * N_INST, NATT * DATT, 2 * RF, 0LL, 0LL, 0LL, 0LL);
    }
}